// round 8
// baseline (speedup 1.0000x reference)
#include <cuda_runtime.h>
#include <math.h>

// ---------------- scratch (device globals; no allocation allowed) ----------
#define OFF_LIG     0           // 512*128
#define OFF_POC     65536       // 1024*128
#define OFF_M       196608      // 512*1024
#define OFF_MT      720896      // 1024*512
#define OFF_AGGL    1245184     // 512*128
#define OFF_AGGP    1310720     // 1024*128
#define OFF_LIGE    1441792     // 512*128
#define OFF_POCE    1507328     // 1024*128
#define OFF_QKVL    1638400     // 512*384
#define OFF_QKVP    1835008     // 1024*384
#define OFF_ATTL    2228224     // 512*128
#define OFF_ATTP    2293760     // 1024*128
#define OFF_TAB     2424832     // 4096
#define SCRATCH_FLOATS 2428928

__device__ float g_scratch[SCRATCH_FLOATS];

#define TAB_N 4096
#define D_MAX 35.0f

// ---------------- k_pre: table build (blocks 0..31) + input proj (32..127) ---
__global__ void __launch_bounds__(128) k_pre(const float* __restrict__ Wd1,
                                             const float* __restrict__ bd1,
                                             const float* __restrict__ Wd2,
                                             const float* __restrict__ bd2,
                                             const float* __restrict__ Wd3,
                                             const float* __restrict__ bd3,
                                             float* __restrict__ tab,
                                             const float* __restrict__ lf,
                                             const float* __restrict__ pf,
                                             const float* __restrict__ Wl,
                                             const float* __restrict__ bl,
                                             const float* __restrict__ Wp,
                                             const float* __restrict__ bp,
                                             float* __restrict__ lig,
                                             float* __restrict__ poc) {
    __shared__ __align__(16) float sbuf[2048];  // Wd2 (table) or Xs (proj)
    __shared__ float w1s[32], b1s[32], b2s[64], wms[64], mcs;
    int tid = threadIdx.x, bx = blockIdx.x;

    if (bx < 32) {
        // ---- table: tab[i] = m(d_i) with mean-folded last layer ----
        for (int idx = tid; idx < 2048; idx += 128) sbuf[idx] = Wd2[idx];
        if (tid < 32) { w1s[tid] = Wd1[tid]; b1s[tid] = bd1[tid]; }
        if (tid >= 32 && tid < 96) b2s[tid - 32] = bd2[tid - 32];
        if (tid < 64) {
            float s = 0.f;
            for (int i = 0; i < 128; i++) s += Wd3[i * 64 + tid];
            wms[tid] = s * (1.f / 128.f);
        }
        if (tid == 127) {
            float s = 0.f;
            for (int i = 0; i < 128; i++) s += bd3[i];
            mcs = s * (1.f / 128.f);
        }
        __syncthreads();
        int idx = bx * 128 + tid;
        float d = (float)idx * (D_MAX / (float)(TAB_N - 1));
        float h1[32];
        #pragma unroll
        for (int k = 0; k < 32; k++) h1[k] = fmaxf(fmaf(d, w1s[k], b1s[k]), 0.f);
        float mval = mcs;
        #pragma unroll 1
        for (int j = 0; j < 64; j++) {
            const float4* wr = (const float4*)(sbuf + j * 32);
            float a0 = 0.f, a1 = 0.f, a2 = 0.f, a3 = 0.f;
            #pragma unroll
            for (int q = 0; q < 8; q++) {
                float4 w = wr[q];
                a0 = fmaf(w.x, h1[4 * q + 0], a0);
                a1 = fmaf(w.y, h1[4 * q + 1], a1);
                a2 = fmaf(w.z, h1[4 * q + 2], a2);
                a3 = fmaf(w.w, h1[4 * q + 3], a3);
            }
            float pre = b2s[j] + ((a0 + a1) + (a2 + a3));
            mval = fmaf(fmaxf(pre, 0.f), wms[j], mval);
        }
        tab[idx] = mval;
    } else {
        // ---- input projections: 16 rows/block ----
        int pb = bx - 32;
        const float* X; const float* W; const float* B; float* Y; int r0;
        if (pb < 32) { X = lf; W = Wl; B = bl; Y = lig; r0 = pb * 16; }
        else         { X = pf; W = Wp; B = bp; Y = poc; r0 = (pb - 32) * 16; }
        const float4* xsrc = (const float4*)(X + (size_t)r0 * 128);
        for (int idx = tid; idx < 512; idx += 128) ((float4*)sbuf)[idx] = xsrc[idx];
        __syncthreads();
        float acc[16];
        float bv = B[tid];
        #pragma unroll
        for (int r = 0; r < 16; r++) acc[r] = bv;
        const float* w = W + (size_t)tid * 128;
        #pragma unroll 4
        for (int k = 0; k < 128; k++) {
            float wv = w[k];
            #pragma unroll
            for (int r = 0; r < 16; r++) acc[r] = fmaf(sbuf[r * 128 + k], wv, acc[r]);
        }
        #pragma unroll
        for (int r = 0; r < 16; r++) Y[(size_t)(r0 + r) * 128 + tid] = acc[r];
    }
}

// ---------------- pair: m via table lerp, write M and MT ----------------------
// grid 128 (4 lig rows each), block 256.
__global__ void __launch_bounds__(256) k_pairm(const float* __restrict__ lc,
                                               const float* __restrict__ pc,
                                               const float* __restrict__ tab,
                                               float* __restrict__ M,
                                               float* __restrict__ MT) {
    __shared__ float tabs[TAB_N];
    __shared__ float pcs[3072];
    int tid = threadIdx.x;
    for (int idx = tid; idx < TAB_N; idx += 256) tabs[idx] = tab[idx];
    for (int idx = tid; idx < 3072; idx += 256) pcs[idx] = pc[idx];
    __syncthreads();

    int i0 = blockIdx.x * 4;
    float lx[4], ly[4], lz[4];
    #pragma unroll
    for (int r = 0; r < 4; r++) {
        lx[r] = lc[(i0 + r) * 3 + 0];
        ly[r] = lc[(i0 + r) * 3 + 1];
        lz[r] = lc[(i0 + r) * 3 + 2];
    }
    const float invh = (float)(TAB_N - 1) / D_MAX;
    #pragma unroll
    for (int jj = 0; jj < 4; jj++) {
        int j = jj * 256 + tid;
        float px = pcs[j * 3 + 0], py = pcs[j * 3 + 1], pz = pcs[j * 3 + 2];
        float4 v;
        float* vp = (float*)&v;
        #pragma unroll
        for (int r = 0; r < 4; r++) {
            float dx = lx[r] - px, dy = ly[r] - py, dz = lz[r] - pz;
            float d = sqrtf(fmaf(dx, dx, fmaf(dy, dy, dz * dz)));
            float t = d * invh;
            int t0 = min((int)t, TAB_N - 2);
            float f = t - (float)t0;
            float v0 = tabs[t0], v1 = tabs[t0 + 1];
            vp[r] = fmaf(f, v1 - v0, v0);
            M[(size_t)(i0 + r) * 1024 + j] = vp[r];
        }
        *(float4*)(MT + (size_t)j * 512 + i0) = v;
    }
}

// ---------------- agg with fused spatial softmax -------------------------------
// grid 192 (64 lig-blocks + 128 poc-blocks of 8 rows), block 256 = 8 warps.
// Warp w: softmax(-src[row w]) -> weights into As[k][8]; then GEMM phase.
__global__ void __launch_bounds__(256) k_aggsoft(const float* __restrict__ M,
                                                 const float* __restrict__ MT,
                                                 const float* __restrict__ poc,
                                                 const float* __restrict__ lig,
                                                 float* __restrict__ aggl,
                                                 float* __restrict__ aggp) {
    __shared__ __align__(16) float As[1024 * 8];
    int tid = threadIdx.x, bx = blockIdx.x;
    const float* S; const float* B; float* Y; int r0, K;
    if (bx < 64) { S = M;  B = poc; Y = aggl; r0 = bx * 8;        K = 1024; }
    else         { S = MT; B = lig; Y = aggp; r0 = (bx - 64) * 8; K = 512;  }

    // softmax phase: warp per row
    int w = tid >> 5, lane = tid & 31;
    int ne = K >> 5;  // elems per lane (32 or 16)
    const float* srow = S + (size_t)(r0 + w) * K;
    float mv[32];
    float mx = -3.4e38f;
    for (int t = 0; t < ne; t++) {
        float v = -srow[t * 32 + lane];
        mv[t] = v;
        mx = fmaxf(mx, v);
    }
    #pragma unroll
    for (int o = 16; o > 0; o >>= 1) mx = fmaxf(mx, __shfl_xor_sync(0xffffffffu, mx, o));
    float sum = 0.f;
    for (int t = 0; t < ne; t++) {
        float e = __expf(mv[t] - mx);
        mv[t] = e;
        sum += e;
    }
    #pragma unroll
    for (int o = 16; o > 0; o >>= 1) sum += __shfl_xor_sync(0xffffffffu, sum, o);
    float inv = 1.f / sum;
    for (int t = 0; t < ne; t++) As[(t * 32 + lane) * 8 + w] = mv[t] * inv;
    __syncthreads();

    // GEMM phase: thread = (col, K-half)
    int c = tid & 127, half = tid >> 7;
    int khalf = K >> 1;
    int ks = half * khalf;
    float acc[8];
    #pragma unroll
    for (int r = 0; r < 8; r++) acc[r] = 0.f;
    const float4* As4 = (const float4*)As;
    #pragma unroll 4
    for (int kk = 0; kk < khalf; kk++) {
        int k = ks + kk;
        float b = B[(size_t)k * 128 + c];
        float4 a0 = As4[k * 2 + 0], a1 = As4[k * 2 + 1];
        acc[0] = fmaf(a0.x, b, acc[0]); acc[1] = fmaf(a0.y, b, acc[1]);
        acc[2] = fmaf(a0.z, b, acc[2]); acc[3] = fmaf(a0.w, b, acc[3]);
        acc[4] = fmaf(a1.x, b, acc[4]); acc[5] = fmaf(a1.y, b, acc[5]);
        acc[6] = fmaf(a1.z, b, acc[6]); acc[7] = fmaf(a1.w, b, acc[7]);
    }
    __syncthreads();
    if (half == 1) {
        #pragma unroll
        for (int r = 0; r < 8; r++) As[c * 8 + r] = acc[r];
    }
    __syncthreads();
    if (half == 0) {
        #pragma unroll
        for (int r = 0; r < 8; r++)
            Y[(size_t)(r0 + r) * 128 + c] = acc[r] + As[c * 8 + r];
    }
}

// ---------------- fused gate + qkv projection ----------------------------------
// grid 192 (64 lig + 128 poc blocks of 8 rows), block 128.
__global__ void __launch_bounds__(128) k_gateqkv(const float* __restrict__ lig,
                                                 const float* __restrict__ poc,
                                                 const float* __restrict__ aggl,
                                                 const float* __restrict__ aggp,
                                                 const float* __restrict__ Wgl,
                                                 const float* __restrict__ bgl,
                                                 const float* __restrict__ Wgp,
                                                 const float* __restrict__ bgp,
                                                 const float* __restrict__ Wqkv,
                                                 const float* __restrict__ bqkv,
                                                 float* __restrict__ lige,
                                                 float* __restrict__ poce,
                                                 float* __restrict__ qkvl,
                                                 float* __restrict__ qkvp) {
    __shared__ __align__(16) float xs[8 * 128];
    __shared__ __align__(16) float as_[8 * 128];
    __shared__ __align__(16) float E[8 * 128];
    int tid = threadIdx.x, bx = blockIdx.x;
    const float* X; const float* A; const float* W; const float* B;
    float* Ye; float* Yq; int r0;
    if (bx < 64) { X = lig; A = aggl; W = Wgl; B = bgl; Ye = lige; Yq = qkvl; r0 = bx * 8; }
    else { X = poc; A = aggp; W = Wgp; B = bgp; Ye = poce; Yq = qkvp; r0 = (bx - 64) * 8; }
    for (int idx = tid; idx < 256; idx += 128) {
        ((float4*)xs)[idx] = ((const float4*)(X + (size_t)r0 * 128))[idx];
        ((float4*)as_)[idx] = ((const float4*)(A + (size_t)r0 * 128))[idx];
    }
    __syncthreads();

    // gate
    {
        float acc[8];
        float bv = B[tid];
        #pragma unroll
        for (int r = 0; r < 8; r++) acc[r] = bv;
        const float* w = W + (size_t)tid * 256;
        #pragma unroll 4
        for (int k = 0; k < 128; k++) {
            float wv = w[k];
            #pragma unroll
            for (int r = 0; r < 8; r++) acc[r] = fmaf(xs[r * 128 + k], wv, acc[r]);
        }
        #pragma unroll 4
        for (int k = 0; k < 128; k++) {
            float wv = w[128 + k];
            #pragma unroll
            for (int r = 0; r < 8; r++) acc[r] = fmaf(as_[r * 128 + k], wv, acc[r]);
        }
        #pragma unroll
        for (int r = 0; r < 8; r++) {
            float g = 1.f / (1.f + __expf(-acc[r]));
            float xv = xs[r * 128 + tid], av = as_[r * 128 + tid];
            float e = g * xv + (1.f - g) * av;
            E[r * 128 + tid] = e;
            Ye[(size_t)(r0 + r) * 128 + tid] = e;
        }
    }
    __syncthreads();

    // qkv: 3 passes of 128 cols
    #pragma unroll 1
    for (int p = 0; p < 3; p++) {
        int c = p * 128 + tid;
        float acc[8];
        float bv = bqkv[c];
        #pragma unroll
        for (int r = 0; r < 8; r++) acc[r] = bv;
        const float* w = Wqkv + (size_t)c * 128;
        #pragma unroll 4
        for (int k = 0; k < 128; k++) {
            float wv = w[k];
            #pragma unroll
            for (int r = 0; r < 8; r++) acc[r] = fmaf(E[r * 128 + k], wv, acc[r]);
        }
        #pragma unroll
        for (int r = 0; r < 8; r++) Yq[(size_t)(r0 + r) * 384 + c] = acc[r];
    }
}

// ---------------- merged flash attention (both directions) --------------------
// grid(96, 8), block 512: warp-per-query, online softmax, hd=16.
__global__ void __launch_bounds__(512) k_flash2(const float* __restrict__ qkvl,
                                                const float* __restrict__ qkvp,
                                                float* __restrict__ attl,
                                                float* __restrict__ attp) {
    __shared__ __align__(16) float4 Ks[128 * 5];
    __shared__ __align__(16) float4 Vs[128 * 5];
    int bx = blockIdx.x, h = blockIdx.y;
    int tid = threadIdx.x;
    int w = tid >> 5, lane = tid & 31;
    const float* Qb; const float* KVb; float* outp; int nk, i;
    if (bx < 32) { Qb = qkvl; KVb = qkvp; outp = attl; nk = 1024; i = bx * 16 + w; }
    else         { Qb = qkvp; KVb = qkvl; outp = attp; nk = 512; i = (bx - 32) * 16 + w; }

    const float* qp = Qb + (size_t)i * 384 + h * 16;
    float4 q0 = ((const float4*)qp)[0];
    float4 q1 = ((const float4*)qp)[1];
    float4 q2 = ((const float4*)qp)[2];
    float4 q3 = ((const float4*)qp)[3];

    float m = -3.4e38f, l = 0.f;
    float acc[16];
    #pragma unroll
    for (int d = 0; d < 16; d++) acc[d] = 0.f;

    int jload = tid >> 2, cload = tid & 3;
    const float* kbase = KVb + (size_t)jload * 384 + 128 + h * 16 + cload * 4;

    for (int jb = 0; jb < nk; jb += 128) {
        __syncthreads();
        Ks[jload * 5 + cload] = *(const float4*)(kbase + (size_t)jb * 384);
        Vs[jload * 5 + cload] = *(const float4*)(kbase + (size_t)jb * 384 + 128);
        __syncthreads();

        float s[4];
        #pragma unroll
        for (int jj = 0; jj < 4; jj++) {
            const float4* kr = Ks + (jj * 32 + lane) * 5;
            float4 k0 = kr[0], k1 = kr[1], k2 = kr[2], k3 = kr[3];
            float t = q0.x * k0.x;
            t = fmaf(q0.y, k0.y, t); t = fmaf(q0.z, k0.z, t); t = fmaf(q0.w, k0.w, t);
            t = fmaf(q1.x, k1.x, t); t = fmaf(q1.y, k1.y, t);
            t = fmaf(q1.z, k1.z, t); t = fmaf(q1.w, k1.w, t);
            t = fmaf(q2.x, k2.x, t); t = fmaf(q2.y, k2.y, t);
            t = fmaf(q2.z, k2.z, t); t = fmaf(q2.w, k2.w, t);
            t = fmaf(q3.x, k3.x, t); t = fmaf(q3.y, k3.y, t);
            t = fmaf(q3.z, k3.z, t); t = fmaf(q3.w, k3.w, t);
            s[jj] = t * 0.25f;
        }
        float tmax = fmaxf(fmaxf(s[0], s[1]), fmaxf(s[2], s[3]));
        #pragma unroll
        for (int o = 16; o > 0; o >>= 1)
            tmax = fmaxf(tmax, __shfl_xor_sync(0xffffffffu, tmax, o));
        float mnew = fmaxf(m, tmax);
        float corr = __expf(m - mnew);
        m = mnew;
        l *= corr;
        #pragma unroll
        for (int d = 0; d < 16; d++) acc[d] *= corr;
        #pragma unroll
        for (int jj = 0; jj < 4; jj++) {
            float p = __expf(s[jj] - m);
            l += p;
            const float4* vr = Vs + (jj * 32 + lane) * 5;
            float4 v0 = vr[0], v1 = vr[1], v2 = vr[2], v3 = vr[3];
            acc[0]  = fmaf(p, v0.x, acc[0]);  acc[1]  = fmaf(p, v0.y, acc[1]);
            acc[2]  = fmaf(p, v0.z, acc[2]);  acc[3]  = fmaf(p, v0.w, acc[3]);
            acc[4]  = fmaf(p, v1.x, acc[4]);  acc[5]  = fmaf(p, v1.y, acc[5]);
            acc[6]  = fmaf(p, v1.z, acc[6]);  acc[7]  = fmaf(p, v1.w, acc[7]);
            acc[8]  = fmaf(p, v2.x, acc[8]);  acc[9]  = fmaf(p, v2.y, acc[9]);
            acc[10] = fmaf(p, v2.z, acc[10]); acc[11] = fmaf(p, v2.w, acc[11]);
            acc[12] = fmaf(p, v3.x, acc[12]); acc[13] = fmaf(p, v3.y, acc[13]);
            acc[14] = fmaf(p, v3.z, acc[14]); acc[15] = fmaf(p, v3.w, acc[15]);
        }
    }

    #pragma unroll
    for (int o = 16; o > 0; o >>= 1) l += __shfl_xor_sync(0xffffffffu, l, o);
    #pragma unroll
    for (int d = 0; d < 16; d++) {
        #pragma unroll
        for (int o = 16; o > 0; o >>= 1)
            acc[d] += __shfl_xor_sync(0xffffffffu, acc[d], o);
    }
    float val = 0.f;
    #pragma unroll
    for (int d = 0; d < 16; d++) if (lane == d) val = acc[d];
    if (lane < 16) outp[(size_t)i * 128 + h * 16 + lane] = val * (1.f / l);
}

// ---------------- merged out-proj + residual + LN ------------------------------
// grid 96, block 128.
__global__ void __launch_bounds__(128) k_outln2(const float* __restrict__ attl,
                                                const float* __restrict__ attp,
                                                const float* __restrict__ W,
                                                const float* __restrict__ bias,
                                                const float* __restrict__ lige,
                                                const float* __restrict__ poce,
                                                const float* __restrict__ g_l,
                                                const float* __restrict__ be_l,
                                                const float* __restrict__ g_p,
                                                const float* __restrict__ be_p,
                                                float* __restrict__ out) {
    __shared__ __align__(16) float Xs[16 * 128];
    __shared__ __align__(16) float T[16 * 128];
    __shared__ float mu[16], iv[16];
    int tid = threadIdx.x, bx = blockIdx.x;
    const float* X; const float* R; const float* gg; const float* bb; float* O; int r0;
    if (bx < 32) { X = attl; R = lige; gg = g_l; bb = be_l; O = out; r0 = bx * 16; }
    else { X = attp; R = poce; gg = g_p; bb = be_p; O = out + 512 * 128; r0 = (bx - 32) * 16; }
    for (int idx = tid; idx < 512; idx += 128)
        ((float4*)Xs)[idx] = ((const float4*)(X + (size_t)r0 * 128))[idx];
    __syncthreads();
    float acc[16];
    float bv = bias[tid];
    #pragma unroll
    for (int r = 0; r < 16; r++) acc[r] = bv;
    const float* w = W + (size_t)tid * 128;
    #pragma unroll 4
    for (int k = 0; k < 128; k++) {
        float wv = w[k];
        #pragma unroll
        for (int r = 0; r < 16; r++) acc[r] = fmaf(Xs[r * 128 + k], wv, acc[r]);
    }
    #pragma unroll
    for (int r = 0; r < 16; r++)
        T[r * 128 + tid] = acc[r] + R[(size_t)(r0 + r) * 128 + tid];
    __syncthreads();

    int wrp = tid >> 5, lane = tid & 31;
    #pragma unroll
    for (int rr = 0; rr < 4; rr++) {
        int r = wrp * 4 + rr;
        float t0 = T[r * 128 + lane], t1 = T[r * 128 + lane + 32];
        float t2 = T[r * 128 + lane + 64], t3 = T[r * 128 + lane + 96];
        float s = (t0 + t1) + (t2 + t3);
        #pragma unroll
        for (int o = 16; o > 0; o >>= 1) s += __shfl_xor_sync(0xffffffffu, s, o);
        float mean = s * (1.f / 128.f);
        float d0 = t0 - mean, d1 = t1 - mean, d2 = t2 - mean, d3 = t3 - mean;
        float v = (d0 * d0 + d1 * d1) + (d2 * d2 + d3 * d3);
        #pragma unroll
        for (int o = 16; o > 0; o >>= 1) v += __shfl_xor_sync(0xffffffffu, v, o);
        if (lane == 0) {
            mu[r] = mean;
            iv[r] = rsqrtf(v * (1.f / 128.f) + 1e-5f);
        }
    }
    __syncthreads();
    float gc = gg[tid], bc = bb[tid];
    #pragma unroll
    for (int r = 0; r < 16; r++) {
        float t = T[r * 128 + tid];
        O[(size_t)(r0 + r) * 128 + tid] = (t - mu[r]) * iv[r] * gc + bc;
    }
}

// ---------------- launch ------------------------------------------------------
extern "C" void kernel_launch(void* const* d_in, const int* in_sizes, int n_in,
                              void* d_out, int out_size) {
    const float* lf   = (const float*)d_in[0];
    const float* pf   = (const float*)d_in[1];
    const float* lc   = (const float*)d_in[2];
    const float* pc   = (const float*)d_in[3];
    const float* Wl   = (const float*)d_in[4];
    const float* bl   = (const float*)d_in[5];
    const float* Wp   = (const float*)d_in[6];
    const float* bp   = (const float*)d_in[7];
    const float* Wd1  = (const float*)d_in[8];
    const float* bd1  = (const float*)d_in[9];
    const float* Wd2  = (const float*)d_in[10];
    const float* bd2  = (const float*)d_in[11];
    const float* Wd3  = (const float*)d_in[12];
    const float* bd3  = (const float*)d_in[13];
    const float* Wgl  = (const float*)d_in[14];
    const float* bgl  = (const float*)d_in[15];
    const float* Wgp  = (const float*)d_in[16];
    const float* bgp  = (const float*)d_in[17];
    const float* Wqkv = (const float*)d_in[18];
    const float* bqkv = (const float*)d_in[19];
    const float* Wo   = (const float*)d_in[20];
    const float* bo   = (const float*)d_in[21];
    const float* g_l  = (const float*)d_in[22];
    const float* be_l = (const float*)d_in[23];
    const float* g_p  = (const float*)d_in[24];
    const float* be_p = (const float*)d_in[25];
    float* out = (float*)d_out;

    float* SB = nullptr;
    cudaGetSymbolAddress((void**)&SB, g_scratch);
    float* s_lig  = SB + OFF_LIG;
    float* s_poc  = SB + OFF_POC;
    float* s_m    = SB + OFF_M;
    float* s_mt   = SB + OFF_MT;
    float* s_aggl = SB + OFF_AGGL;
    float* s_aggp = SB + OFF_AGGP;
    float* s_lige = SB + OFF_LIGE;
    float* s_poce = SB + OFF_POCE;
    float* s_qkvl = SB + OFF_QKVL;
    float* s_qkvp = SB + OFF_QKVP;
    float* s_attl = SB + OFF_ATTL;
    float* s_attp = SB + OFF_ATTP;
    float* s_tab  = SB + OFF_TAB;

    k_pre<<<128, 128>>>(Wd1, bd1, Wd2, bd2, Wd3, bd3, s_tab,
                        lf, pf, Wl, bl, Wp, bp, s_lig, s_poc);
    k_pairm<<<128, 256>>>(lc, pc, s_tab, s_m, s_mt);
    k_aggsoft<<<192, 256>>>(s_m, s_mt, s_poc, s_lig, s_aggl, s_aggp);
    k_gateqkv<<<192, 128>>>(s_lig, s_poc, s_aggl, s_aggp, Wgl, bgl, Wgp, bgp,
                            Wqkv, bqkv, s_lige, s_poce, s_qkvl, s_qkvp);
    k_flash2<<<dim3(96, 8), 512>>>(s_qkvl, s_qkvp, s_attl, s_attp);
    k_outln2<<<96, 128>>>(s_attl, s_attp, Wo, bo, s_lige, s_poce,
                          g_l, be_l, g_p, be_p, out);
}

// round 9
// speedup vs baseline: 1.0786x; 1.0786x over previous
#include <cuda_runtime.h>
#include <math.h>

#define GSZ 148          // persistent grid size (<= SM count, all co-resident)
#define NTHR 512
#define TAB_N 4096
#define D_MAX 35.0f

// ---------------- scratch (device globals) ----------------------------------
#define OFF_LIG     0           // 512*128
#define OFF_POC     65536       // 1024*128
#define OFF_M       196608      // 512*1024
#define OFF_MT      720896      // 1024*512
#define OFF_AGGL    1245184     // 512*128
#define OFF_AGGP    1310720     // 1024*128
#define OFF_LIGE    1441792     // 512*128
#define OFF_POCE    1507328     // 1024*128
#define OFF_QKVL    1638400     // 512*384
#define OFF_QKVP    1835008     // 1024*384
#define OFF_ATTL    2228224     // 512*128
#define OFF_ATTP    2293760     // 1024*128
#define OFF_TAB     2424832     // 4096
#define SCRATCH_FLOATS 2428928

__device__ float g_scratch[SCRATCH_FLOATS];
__device__ unsigned g_bar[8];   // zero-initialized; monotonic tickets

// ---------------- grid barrier (monotonic, replay-safe) ----------------------
__device__ __forceinline__ void gbar(int s) {
    __threadfence();
    __syncthreads();
    if (threadIdx.x == 0) {
        unsigned ticket = atomicAdd(&g_bar[s], 1u);
        unsigned target = (ticket / (unsigned)GSZ + 1u) * (unsigned)GSZ;
        while ((int)(*(volatile unsigned*)&g_bar[s] - target) < 0) {}
        __threadfence();
    }
    __syncthreads();
}

// =============================================================================
__global__ void __launch_bounds__(NTHR, 1) k_persist(
    const float* __restrict__ lf,   const float* __restrict__ pf,
    const float* __restrict__ lc,   const float* __restrict__ pc,
    const float* __restrict__ Wl,   const float* __restrict__ bl,
    const float* __restrict__ Wp,   const float* __restrict__ bp,
    const float* __restrict__ Wd1,  const float* __restrict__ bd1,
    const float* __restrict__ Wd2,  const float* __restrict__ bd2,
    const float* __restrict__ Wd3,  const float* __restrict__ bd3,
    const float* __restrict__ Wgl,  const float* __restrict__ bgl,
    const float* __restrict__ Wgp,  const float* __restrict__ bgp,
    const float* __restrict__ Wqkv, const float* __restrict__ bqkv,
    const float* __restrict__ Wo,   const float* __restrict__ bo,
    const float* __restrict__ g_l,  const float* __restrict__ be_l,
    const float* __restrict__ g_p,  const float* __restrict__ be_p,
    float* __restrict__ out)
{
    extern __shared__ __align__(16) char smem_raw[];
    const int bid = blockIdx.x;
    const int tid = threadIdx.x;

    float* SB = g_scratch;
    float* s_lig  = SB + OFF_LIG;
    float* s_poc  = SB + OFF_POC;
    float* s_m    = SB + OFF_M;
    float* s_mt   = SB + OFF_MT;
    float* s_aggl = SB + OFF_AGGL;
    float* s_aggp = SB + OFF_AGGP;
    float* s_lige = SB + OFF_LIGE;
    float* s_poce = SB + OFF_POCE;
    float* s_qkvl = SB + OFF_QKVL;
    float* s_qkvp = SB + OFF_QKVP;
    float* s_attl = SB + OFF_ATTL;
    float* s_attp = SB + OFF_ATTP;
    float* s_tab  = SB + OFF_TAB;

    // ============== P0: distance table (bid<32) + input proj (32<=bid<128) ====
    {
        float* sbuf = (float*)smem_raw;       // 2048 floats
        float* w1s  = sbuf + 2048;            // 32
        float* b1s  = w1s + 32;               // 32
        float* b2s  = b1s + 32;               // 64
        float* wms  = b2s + 64;               // 64
        float* mcs  = wms + 64;               // 1
        bool act = (bid < 128) && (tid < 128);
        bool istab = bid < 32;
        if (act) {
            if (istab) {
                for (int idx = tid; idx < 2048; idx += 128) sbuf[idx] = Wd2[idx];
                if (tid < 32) { w1s[tid] = Wd1[tid]; b1s[tid] = bd1[tid]; }
                if (tid >= 32 && tid < 96) b2s[tid - 32] = bd2[tid - 32];
                if (tid < 64) {
                    float s = 0.f;
                    for (int i = 0; i < 128; i++) s += Wd3[i * 64 + tid];
                    wms[tid] = s * (1.f / 128.f);
                }
                if (tid == 127) {
                    float s = 0.f;
                    for (int i = 0; i < 128; i++) s += bd3[i];
                    *mcs = s * (1.f / 128.f);
                }
            } else {
                int pb = bid - 32;
                const float* X = (pb < 32) ? lf : pf;
                int r0 = (pb < 32) ? pb * 16 : (pb - 32) * 16;
                const float4* xsrc = (const float4*)(X + (size_t)r0 * 128);
                for (int idx = tid; idx < 512; idx += 128)
                    ((float4*)sbuf)[idx] = xsrc[idx];
            }
        }
        __syncthreads();
        if (act) {
            if (istab) {
                int idx = bid * 128 + tid;
                float d = (float)idx * (D_MAX / (float)(TAB_N - 1));
                float h1[32];
                #pragma unroll
                for (int k = 0; k < 32; k++)
                    h1[k] = fmaxf(fmaf(d, w1s[k], b1s[k]), 0.f);
                float mval = *mcs;
                #pragma unroll 1
                for (int j = 0; j < 64; j++) {
                    const float4* wr = (const float4*)(sbuf + j * 32);
                    float a0 = 0.f, a1 = 0.f, a2 = 0.f, a3 = 0.f;
                    #pragma unroll
                    for (int q = 0; q < 8; q++) {
                        float4 w = wr[q];
                        a0 = fmaf(w.x, h1[4 * q + 0], a0);
                        a1 = fmaf(w.y, h1[4 * q + 1], a1);
                        a2 = fmaf(w.z, h1[4 * q + 2], a2);
                        a3 = fmaf(w.w, h1[4 * q + 3], a3);
                    }
                    float pre = b2s[j] + ((a0 + a1) + (a2 + a3));
                    mval = fmaf(fmaxf(pre, 0.f), wms[j], mval);
                }
                s_tab[idx] = mval;
            } else {
                int pb = bid - 32;
                const float* W; const float* B; float* Y; int r0;
                if (pb < 32) { W = Wl; B = bl; Y = s_lig; r0 = pb * 16; }
                else         { W = Wp; B = bp; Y = s_poc; r0 = (pb - 32) * 16; }
                float acc[16];
                float bv = B[tid];
                #pragma unroll
                for (int r = 0; r < 16; r++) acc[r] = bv;
                const float* w = W + (size_t)tid * 128;
                #pragma unroll 4
                for (int k = 0; k < 128; k++) {
                    float wv = w[k];
                    #pragma unroll
                    for (int r = 0; r < 16; r++)
                        acc[r] = fmaf(sbuf[r * 128 + k], wv, acc[r]);
                }
                #pragma unroll
                for (int r = 0; r < 16; r++)
                    Y[(size_t)(r0 + r) * 128 + tid] = acc[r];
            }
        }
    }
    gbar(0);

    // ============== P1: pair m via table lerp -> M, MT ========================
    {
        float* tabs = (float*)smem_raw;       // 4096
        float* pcs  = tabs + TAB_N;           // 3072
        bool act = (bid < 128) && (tid < 256);
        if (act) {
            for (int idx = tid; idx < TAB_N; idx += 256) tabs[idx] = s_tab[idx];
            for (int idx = tid; idx < 3072; idx += 256) pcs[idx] = pc[idx];
        }
        __syncthreads();
        if (act) {
            int i0 = bid * 4;
            float lx[4], ly[4], lz[4];
            #pragma unroll
            for (int r = 0; r < 4; r++) {
                lx[r] = lc[(i0 + r) * 3 + 0];
                ly[r] = lc[(i0 + r) * 3 + 1];
                lz[r] = lc[(i0 + r) * 3 + 2];
            }
            const float invh = (float)(TAB_N - 1) / D_MAX;
            #pragma unroll
            for (int jj = 0; jj < 4; jj++) {
                int j = jj * 256 + tid;
                float px = pcs[j * 3 + 0], py = pcs[j * 3 + 1], pz = pcs[j * 3 + 2];
                float4 v;
                float* vp = (float*)&v;
                #pragma unroll
                for (int r = 0; r < 4; r++) {
                    float dx = lx[r] - px, dy = ly[r] - py, dz = lz[r] - pz;
                    float d = sqrtf(fmaf(dx, dx, fmaf(dy, dy, dz * dz)));
                    float t = d * invh;
                    int t0 = min((int)t, TAB_N - 2);
                    float f = t - (float)t0;
                    float v0 = tabs[t0], v1 = tabs[t0 + 1];
                    vp[r] = fmaf(f, v1 - v0, v0);
                    s_m[(size_t)(i0 + r) * 1024 + j] = vp[r];
                }
                *(float4*)(s_mt + (size_t)j * 512 + i0) = v;
            }
        }
    }
    gbar(1);

    // ============== P2: softmax + agg GEMM (192 virtual, 2 per block) =========
    {
        int sub = tid >> 8, st = tid & 255;
        int vb = bid * 2 + sub;
        bool act = vb < 192;
        float* As = (float*)smem_raw + sub * 8192;
        const float* S; const float* B; float* Y; int r0 = 0, K = 1024;
        S = s_m; B = s_poc; Y = s_aggl;
        if (act) {
            if (vb < 64) { r0 = vb * 8; }
            else { S = s_mt; B = s_lig; Y = s_aggp; r0 = (vb - 64) * 8; K = 512; }
        }
        // softmax phase: warp per row
        if (act) {
            int w = st >> 5, lane = st & 31;
            int ne = K >> 5;
            const float* srow = S + (size_t)(r0 + w) * K;
            float mv[32];
            float mx = -3.4e38f;
            for (int t = 0; t < ne; t++) {
                float v = -srow[t * 32 + lane];
                mv[t] = v;
                mx = fmaxf(mx, v);
            }
            #pragma unroll
            for (int o = 16; o > 0; o >>= 1)
                mx = fmaxf(mx, __shfl_xor_sync(0xffffffffu, mx, o));
            float sum = 0.f;
            for (int t = 0; t < ne; t++) {
                float e = __expf(mv[t] - mx);
                mv[t] = e;
                sum += e;
            }
            #pragma unroll
            for (int o = 16; o > 0; o >>= 1)
                sum += __shfl_xor_sync(0xffffffffu, sum, o);
            float inv = 1.f / sum;
            for (int t = 0; t < ne; t++) As[(t * 32 + lane) * 8 + w] = mv[t] * inv;
        }
        __syncthreads();
        // GEMM phase
        float acc[8];
        #pragma unroll
        for (int r = 0; r < 8; r++) acc[r] = 0.f;
        int c = st & 127, half = st >> 7;
        if (act) {
            int khalf = K >> 1;
            int ks = half * khalf;
            const float4* As4 = (const float4*)As;
            #pragma unroll 4
            for (int kk = 0; kk < khalf; kk++) {
                int k = ks + kk;
                float b = B[(size_t)k * 128 + c];
                float4 a0 = As4[k * 2 + 0], a1 = As4[k * 2 + 1];
                acc[0] = fmaf(a0.x, b, acc[0]); acc[1] = fmaf(a0.y, b, acc[1]);
                acc[2] = fmaf(a0.z, b, acc[2]); acc[3] = fmaf(a0.w, b, acc[3]);
                acc[4] = fmaf(a1.x, b, acc[4]); acc[5] = fmaf(a1.y, b, acc[5]);
                acc[6] = fmaf(a1.z, b, acc[6]); acc[7] = fmaf(a1.w, b, acc[7]);
            }
        }
        __syncthreads();
        if (act && half == 1) {
            #pragma unroll
            for (int r = 0; r < 8; r++) As[c * 8 + r] = acc[r];
        }
        __syncthreads();
        if (act && half == 0) {
            #pragma unroll
            for (int r = 0; r < 8; r++)
                Y[(size_t)(r0 + r) * 128 + c] = acc[r] + As[c * 8 + r];
        }
    }
    gbar(2);

    // ============== P3: gate (96 virtual, 16 rows, 128t) =======================
    {
        float* xs  = (float*)smem_raw;          // 2048
        float* as_ = xs + 2048;                  // 2048
        bool act = (bid < 96) && (tid < 128);
        const float* X; const float* A; const float* W; const float* B;
        float* Y; int r0 = 0;
        X = s_lig; A = s_aggl; W = Wgl; B = bgl; Y = s_lige;
        if (act) {
            if (bid < 32) { r0 = bid * 16; }
            else { X = s_poc; A = s_aggp; W = Wgp; B = bgp; Y = s_poce; r0 = (bid - 32) * 16; }
            for (int idx = tid; idx < 512; idx += 128) {
                ((float4*)xs)[idx] = ((const float4*)(X + (size_t)r0 * 128))[idx];
                ((float4*)as_)[idx] = ((const float4*)(A + (size_t)r0 * 128))[idx];
            }
        }
        __syncthreads();
        if (act) {
            float acc[16];
            float bv = B[tid];
            #pragma unroll
            for (int r = 0; r < 16; r++) acc[r] = bv;
            const float* w = W + (size_t)tid * 256;
            #pragma unroll 4
            for (int k = 0; k < 128; k++) {
                float wv = w[k];
                #pragma unroll
                for (int r = 0; r < 16; r++) acc[r] = fmaf(xs[r * 128 + k], wv, acc[r]);
            }
            #pragma unroll 4
            for (int k = 0; k < 128; k++) {
                float wv = w[128 + k];
                #pragma unroll
                for (int r = 0; r < 16; r++) acc[r] = fmaf(as_[r * 128 + k], wv, acc[r]);
            }
            #pragma unroll
            for (int r = 0; r < 16; r++) {
                float g = 1.f / (1.f + __expf(-acc[r]));
                float xv = xs[r * 128 + tid], av = as_[r * 128 + tid];
                Y[(size_t)(r0 + r) * 128 + tid] = g * xv + (1.f - g) * av;
            }
        }
    }
    gbar(3);

    // ============== P4: qkv projection (288 virtual of 128t, 4 per block) =====
    {
        int sub = tid >> 7, st = tid & 127;
        int vb = bid * 4 + sub;
        bool act = vb < 288;
        float* Xs = (float*)smem_raw + sub * 2048;
        const float* X = s_lige; float* Y = s_qkvl; int r0 = 0, p = 0, tile = 0;
        if (act) {
            p = vb / 96;
            tile = vb % 96;
            if (tile < 32) { r0 = tile * 16; }
            else { X = s_poce; Y = s_qkvp; r0 = (tile - 32) * 16; }
            for (int idx = st; idx < 512; idx += 128)
                ((float4*)Xs)[idx] = ((const float4*)(X + (size_t)r0 * 128))[idx];
        }
        __syncthreads();
        if (act) {
            int c = p * 128 + st;
            float acc[16];
            float bv = bqkv[c];
            #pragma unroll
            for (int r = 0; r < 16; r++) acc[r] = bv;
            const float* w = Wqkv + (size_t)c * 128;
            #pragma unroll 4
            for (int k = 0; k < 128; k++) {
                float wv = w[k];
                #pragma unroll
                for (int r = 0; r < 16; r++) acc[r] = fmaf(Xs[r * 128 + k], wv, acc[r]);
            }
            #pragma unroll
            for (int r = 0; r < 16; r++) Y[(size_t)(r0 + r) * 384 + c] = acc[r];
        }
    }
    gbar(4);

    // ============== P5: flash attention (768 virtual, loop) =====================
    {
        float4* Ks = (float4*)smem_raw;          // 128*5
        float4* Vs = Ks + 128 * 5;               // 128*5
        int w = tid >> 5, lane = tid & 31;
        for (int vb = bid; vb < 768; vb += GSZ) {
            int h = vb / 96, bx = vb % 96;
            const float* Qb; const float* KVb; float* outp; int nk, i;
            if (bx < 32) { Qb = s_qkvl; KVb = s_qkvp; outp = s_attl; nk = 1024; i = bx * 16 + w; }
            else         { Qb = s_qkvp; KVb = s_qkvl; outp = s_attp; nk = 512; i = (bx - 32) * 16 + w; }

            const float* qp = Qb + (size_t)i * 384 + h * 16;
            float4 q0 = ((const float4*)qp)[0];
            float4 q1 = ((const float4*)qp)[1];
            float4 q2 = ((const float4*)qp)[2];
            float4 q3 = ((const float4*)qp)[3];

            float m = -3.4e38f, l = 0.f;
            float acc[16];
            #pragma unroll
            for (int d = 0; d < 16; d++) acc[d] = 0.f;

            int jload = tid >> 2, cload = tid & 3;
            const float* kbase = KVb + (size_t)jload * 384 + 128 + h * 16 + cload * 4;

            for (int jb = 0; jb < nk; jb += 128) {
                __syncthreads();
                Ks[jload * 5 + cload] = *(const float4*)(kbase + (size_t)jb * 384);
                Vs[jload * 5 + cload] = *(const float4*)(kbase + (size_t)jb * 384 + 128);
                __syncthreads();

                float s[4];
                #pragma unroll
                for (int jj = 0; jj < 4; jj++) {
                    const float4* kr = Ks + (jj * 32 + lane) * 5;
                    float4 k0 = kr[0], k1 = kr[1], k2 = kr[2], k3 = kr[3];
                    float t = q0.x * k0.x;
                    t = fmaf(q0.y, k0.y, t); t = fmaf(q0.z, k0.z, t); t = fmaf(q0.w, k0.w, t);
                    t = fmaf(q1.x, k1.x, t); t = fmaf(q1.y, k1.y, t);
                    t = fmaf(q1.z, k1.z, t); t = fmaf(q1.w, k1.w, t);
                    t = fmaf(q2.x, k2.x, t); t = fmaf(q2.y, k2.y, t);
                    t = fmaf(q2.z, k2.z, t); t = fmaf(q2.w, k2.w, t);
                    t = fmaf(q3.x, k3.x, t); t = fmaf(q3.y, k3.y, t);
                    t = fmaf(q3.z, k3.z, t); t = fmaf(q3.w, k3.w, t);
                    s[jj] = t * 0.25f;
                }
                float tmax = fmaxf(fmaxf(s[0], s[1]), fmaxf(s[2], s[3]));
                #pragma unroll
                for (int o = 16; o > 0; o >>= 1)
                    tmax = fmaxf(tmax, __shfl_xor_sync(0xffffffffu, tmax, o));
                float mnew = fmaxf(m, tmax);
                float corr = __expf(m - mnew);
                m = mnew;
                l *= corr;
                #pragma unroll
                for (int d = 0; d < 16; d++) acc[d] *= corr;
                #pragma unroll
                for (int jj = 0; jj < 4; jj++) {
                    float p = __expf(s[jj] - m);
                    l += p;
                    const float4* vr = Vs + (jj * 32 + lane) * 5;
                    float4 v0 = vr[0], v1 = vr[1], v2 = vr[2], v3 = vr[3];
                    acc[0]  = fmaf(p, v0.x, acc[0]);  acc[1]  = fmaf(p, v0.y, acc[1]);
                    acc[2]  = fmaf(p, v0.z, acc[2]);  acc[3]  = fmaf(p, v0.w, acc[3]);
                    acc[4]  = fmaf(p, v1.x, acc[4]);  acc[5]  = fmaf(p, v1.y, acc[5]);
                    acc[6]  = fmaf(p, v1.z, acc[6]);  acc[7]  = fmaf(p, v1.w, acc[7]);
                    acc[8]  = fmaf(p, v2.x, acc[8]);  acc[9]  = fmaf(p, v2.y, acc[9]);
                    acc[10] = fmaf(p, v2.z, acc[10]); acc[11] = fmaf(p, v2.w, acc[11]);
                    acc[12] = fmaf(p, v3.x, acc[12]); acc[13] = fmaf(p, v3.y, acc[13]);
                    acc[14] = fmaf(p, v3.z, acc[14]); acc[15] = fmaf(p, v3.w, acc[15]);
                }
            }

            #pragma unroll
            for (int o = 16; o > 0; o >>= 1) l += __shfl_xor_sync(0xffffffffu, l, o);
            #pragma unroll
            for (int d = 0; d < 16; d++) {
                #pragma unroll
                for (int o = 16; o > 0; o >>= 1)
                    acc[d] += __shfl_xor_sync(0xffffffffu, acc[d], o);
            }
            float val = 0.f;
            #pragma unroll
            for (int d = 0; d < 16; d++) if (lane == d) val = acc[d];
            if (lane < 16) outp[(size_t)i * 128 + h * 16 + lane] = val * (1.f / l);
            __syncthreads();
        }
    }
    gbar(5);

    // ============== P6: out-proj + residual + LayerNorm (96 virtual, 128t) =====
    {
        float* Xs = (float*)smem_raw;            // 2048
        float* T  = Xs + 2048;                    // 2048
        float* mu = T + 2048;                     // 16
        float* iv = mu + 16;                      // 16
        bool act = (bid < 96) && (tid < 128);
        const float* X = s_attl; const float* R = s_lige;
        const float* gg = g_l; const float* bb = be_l;
        float* O = out; int r0 = 0;
        if (act) {
            if (bid < 32) { r0 = bid * 16; }
            else {
                X = s_attp; R = s_poce; gg = g_p; bb = be_p;
                O = out + 512 * 128; r0 = (bid - 32) * 16;
            }
            for (int idx = tid; idx < 512; idx += 128)
                ((float4*)Xs)[idx] = ((const float4*)(X + (size_t)r0 * 128))[idx];
        }
        __syncthreads();
        if (act) {
            float acc[16];
            float bv = bo[tid];
            #pragma unroll
            for (int r = 0; r < 16; r++) acc[r] = bv;
            const float* w = Wo + (size_t)tid * 128;
            #pragma unroll 4
            for (int k = 0; k < 128; k++) {
                float wv = w[k];
                #pragma unroll
                for (int r = 0; r < 16; r++) acc[r] = fmaf(Xs[r * 128 + k], wv, acc[r]);
            }
            #pragma unroll
            for (int r = 0; r < 16; r++)
                T[r * 128 + tid] = acc[r] + R[(size_t)(r0 + r) * 128 + tid];
        }
        __syncthreads();
        if (act) {
            int wrp = tid >> 5, lane = tid & 31;
            #pragma unroll
            for (int rr = 0; rr < 4; rr++) {
                int r = wrp * 4 + rr;
                float t0 = T[r * 128 + lane], t1 = T[r * 128 + lane + 32];
                float t2 = T[r * 128 + lane + 64], t3 = T[r * 128 + lane + 96];
                float s = (t0 + t1) + (t2 + t3);
                #pragma unroll
                for (int o = 16; o > 0; o >>= 1)
                    s += __shfl_xor_sync(0xffffffffu, s, o);
                float mean = s * (1.f / 128.f);
                float d0 = t0 - mean, d1 = t1 - mean, d2 = t2 - mean, d3 = t3 - mean;
                float v = (d0 * d0 + d1 * d1) + (d2 * d2 + d3 * d3);
                #pragma unroll
                for (int o = 16; o > 0; o >>= 1)
                    v += __shfl_xor_sync(0xffffffffu, v, o);
                if (lane == 0) {
                    mu[r] = mean;
                    iv[r] = rsqrtf(v * (1.f / 128.f) + 1e-5f);
                }
            }
        }
        __syncthreads();
        if (act) {
            float gc = gg[tid], bc = bb[tid];
            #pragma unroll
            for (int r = 0; r < 16; r++) {
                float t = T[r * 128 + tid];
                O[(size_t)(r0 + r) * 128 + tid] = (t - mu[r]) * iv[r] * gc + bc;
            }
        }
    }
}

// ---------------- launch ------------------------------------------------------
extern "C" void kernel_launch(void* const* d_in, const int* in_sizes, int n_in,
                              void* d_out, int out_size) {
    static bool s_attr_set = false;
    if (!s_attr_set) {
        cudaFuncSetAttribute(k_persist,
                             cudaFuncAttributeMaxDynamicSharedMemorySize, 66560);
        s_attr_set = true;
    }
    k_persist<<<GSZ, NTHR, 66560>>>(
        (const float*)d_in[0],  (const float*)d_in[1],
        (const float*)d_in[2],  (const float*)d_in[3],
        (const float*)d_in[4],  (const float*)d_in[5],
        (const float*)d_in[6],  (const float*)d_in[7],
        (const float*)d_in[8],  (const float*)d_in[9],
        (const float*)d_in[10], (const float*)d_in[11],
        (const float*)d_in[12], (const float*)d_in[13],
        (const float*)d_in[14], (const float*)d_in[15],
        (const float*)d_in[16], (const float*)d_in[17],
        (const float*)d_in[18], (const float*)d_in[19],
        (const float*)d_in[20], (const float*)d_in[21],
        (const float*)d_in[22], (const float*)d_in[23],
        (const float*)d_in[24], (const float*)d_in[25],
        (float*)d_out);
}

// round 10
// speedup vs baseline: 1.5106x; 1.4006x over previous
#include <cuda_runtime.h>
#include <math.h>

// ---------------- scratch (device globals; no allocation allowed) ----------
#define OFF_LIG     0           // 512*128
#define OFF_POC     65536       // 1024*128
#define OFF_M       196608      // 512*1024
#define OFF_MT      720896      // 1024*512
#define OFF_AGGL    1245184     // 512*128
#define OFF_AGGP    1310720     // 1024*128
#define OFF_LIGE    1441792     // 512*128
#define OFF_POCE    1507328     // 1024*128
#define OFF_QKVL    1638400     // 512*384
#define OFF_QKVP    1835008     // 1024*384
#define OFF_ATTL    2228224     // 512*128
#define OFF_ATTP    2293760     // 1024*128
#define OFF_TAB     2424832     // 4096
#define SCRATCH_FLOATS 2428928

__device__ float g_scratch[SCRATCH_FLOATS];

#define TAB_N 4096
#define D_MAX 35.0f

// ---------------- k_pre: 64 blocks x 256 (2 subtiles). subs 0..31 table,
//                  subs 32..127 input projections (16 rows, float4-k GEMM) ----
__global__ void __launch_bounds__(256) k_pre(const float* __restrict__ Wd1,
                                             const float* __restrict__ bd1,
                                             const float* __restrict__ Wd2,
                                             const float* __restrict__ bd2,
                                             const float* __restrict__ Wd3,
                                             const float* __restrict__ bd3,
                                             float* __restrict__ tab,
                                             const float* __restrict__ lf,
                                             const float* __restrict__ pf,
                                             const float* __restrict__ Wl,
                                             const float* __restrict__ bl,
                                             const float* __restrict__ Wp,
                                             const float* __restrict__ bp,
                                             float* __restrict__ lig,
                                             float* __restrict__ poc) {
    __shared__ __align__(16) float smem[2 * 2304];
    int tid = threadIdx.x;
    int sub = tid >> 7, st = tid & 127;
    int vb = blockIdx.x * 2 + sub;
    float* sbuf = smem + sub * 2304;          // 2048 data
    float* w1s = sbuf + 2048;                 // 32
    float* b1s = w1s + 32;                    // 32
    float* b2s = b1s + 32;                    // 64
    float* wms = b2s + 64;                    // 64
    float* mcs = wms + 64;                    // 1

    if (vb < 32) {
        // ---- table slice ----
        for (int idx = st; idx < 2048; idx += 128) sbuf[idx] = Wd2[idx];
        if (st < 32) { w1s[st] = Wd1[st]; b1s[st] = bd1[st]; }
        if (st >= 32 && st < 96) b2s[st - 32] = bd2[st - 32];
        if (st < 64) {
            float s = 0.f;
            for (int i = 0; i < 128; i++) s += Wd3[i * 64 + st];
            wms[st] = s * (1.f / 128.f);
        }
        if (st == 127) {
            float s = 0.f;
            for (int i = 0; i < 128; i++) s += bd3[i];
            *mcs = s * (1.f / 128.f);
        }
        __syncthreads();
        int idx = vb * 128 + st;
        float d = (float)idx * (D_MAX / (float)(TAB_N - 1));
        float h1[32];
        #pragma unroll
        for (int k = 0; k < 32; k++) h1[k] = fmaxf(fmaf(d, w1s[k], b1s[k]), 0.f);
        float mval = *mcs;
        #pragma unroll 1
        for (int j = 0; j < 64; j++) {
            const float4* wr = (const float4*)(sbuf + j * 32);
            float a0 = 0.f, a1 = 0.f, a2 = 0.f, a3 = 0.f;
            #pragma unroll
            for (int q = 0; q < 8; q++) {
                float4 w = wr[q];
                a0 = fmaf(w.x, h1[4 * q + 0], a0);
                a1 = fmaf(w.y, h1[4 * q + 1], a1);
                a2 = fmaf(w.z, h1[4 * q + 2], a2);
                a3 = fmaf(w.w, h1[4 * q + 3], a3);
            }
            float pre = b2s[j] + ((a0 + a1) + (a2 + a3));
            mval = fmaf(fmaxf(pre, 0.f), wms[j], mval);
        }
        tab[idx] = mval;
    } else {
        // ---- input projection: 16 rows, float4-k blocked ----
        int pb = vb - 32;
        const float* X; const float* W; const float* B; float* Y; int r0;
        if (pb < 32) { X = lf; W = Wl; B = bl; Y = lig; r0 = pb * 16; }
        else         { X = pf; W = Wp; B = bp; Y = poc; r0 = (pb - 32) * 16; }
        const float4* xsrc = (const float4*)(X + (size_t)r0 * 128);
        for (int idx = st; idx < 512; idx += 128) ((float4*)sbuf)[idx] = xsrc[idx];
        __syncthreads();
        const float4* Xs4 = (const float4*)sbuf;
        float acc[16];
        float bv = B[st];
        #pragma unroll
        for (int r = 0; r < 16; r++) acc[r] = bv;
        const float4* w4 = (const float4*)(W + (size_t)st * 128);
        #pragma unroll 2
        for (int kb = 0; kb < 32; kb++) {
            float4 wv = w4[kb];
            #pragma unroll
            for (int r = 0; r < 16; r++) {
                float4 x = Xs4[r * 32 + kb];
                acc[r] = fmaf(x.x, wv.x, acc[r]);
                acc[r] = fmaf(x.y, wv.y, acc[r]);
                acc[r] = fmaf(x.z, wv.z, acc[r]);
                acc[r] = fmaf(x.w, wv.w, acc[r]);
            }
        }
        #pragma unroll
        for (int r = 0; r < 16; r++) Y[(size_t)(r0 + r) * 128 + st] = acc[r];
    }
}

// ---------------- pair: m via table lerp, write M and MT ----------------------
// grid 128 (4 lig rows each), block 256.
__global__ void __launch_bounds__(256) k_pairm(const float* __restrict__ lc,
                                               const float* __restrict__ pc,
                                               const float* __restrict__ tab,
                                               float* __restrict__ M,
                                               float* __restrict__ MT) {
    __shared__ float tabs[TAB_N];
    __shared__ float pcs[3072];
    int tid = threadIdx.x;
    for (int idx = tid; idx < TAB_N; idx += 256) tabs[idx] = tab[idx];
    for (int idx = tid; idx < 3072; idx += 256) pcs[idx] = pc[idx];
    __syncthreads();

    int i0 = blockIdx.x * 4;
    float lx[4], ly[4], lz[4];
    #pragma unroll
    for (int r = 0; r < 4; r++) {
        lx[r] = lc[(i0 + r) * 3 + 0];
        ly[r] = lc[(i0 + r) * 3 + 1];
        lz[r] = lc[(i0 + r) * 3 + 2];
    }
    const float invh = (float)(TAB_N - 1) / D_MAX;
    #pragma unroll
    for (int jj = 0; jj < 4; jj++) {
        int j = jj * 256 + tid;
        float px = pcs[j * 3 + 0], py = pcs[j * 3 + 1], pz = pcs[j * 3 + 2];
        float4 v;
        float* vp = (float*)&v;
        #pragma unroll
        for (int r = 0; r < 4; r++) {
            float dx = lx[r] - px, dy = ly[r] - py, dz = lz[r] - pz;
            float d = sqrtf(fmaf(dx, dx, fmaf(dy, dy, dz * dz)));
            float t = d * invh;
            int t0 = min((int)t, TAB_N - 2);
            float f = t - (float)t0;
            float v0 = tabs[t0], v1 = tabs[t0 + 1];
            vp[r] = fmaf(f, v1 - v0, v0);
            M[(size_t)(i0 + r) * 1024 + j] = vp[r];
        }
        *(float4*)(MT + (size_t)j * 512 + i0) = v;
    }
}

// ---------------- agg with fused softmax, register-blocked GEMM ---------------
// grid 192, block 256. 8 rows/tile. Softmax warp-per-row (compile-time ne),
// then GEMM: thread = (4 cols, K/8 slice), 32 FMA per 3 loads, smem reduce.
__global__ void __launch_bounds__(256) k_aggsoft(const float* __restrict__ M,
                                                 const float* __restrict__ MT,
                                                 const float* __restrict__ poc,
                                                 const float* __restrict__ lig,
                                                 float* __restrict__ aggl,
                                                 float* __restrict__ aggp) {
    __shared__ __align__(16) float As[8192];
    int tid = threadIdx.x, bx = blockIdx.x;
    const float* S; const float* B; float* Y; int r0, K;
    if (bx < 64) { S = M;  B = poc; Y = aggl; r0 = bx * 8;        K = 1024; }
    else         { S = MT; B = lig; Y = aggp; r0 = (bx - 64) * 8; K = 512;  }

    // ---- softmax phase: warp per row, fully unrolled (no spills) ----
    int w = tid >> 5, lane = tid & 31;
    const float* srow = S + (size_t)(r0 + w) * K;
    if (K == 1024) {
        float mv[32];
        float mx = -3.4e38f;
        #pragma unroll
        for (int t = 0; t < 32; t++) {
            float v = -srow[t * 32 + lane];
            mv[t] = v;
            mx = fmaxf(mx, v);
        }
        #pragma unroll
        for (int o = 16; o > 0; o >>= 1)
            mx = fmaxf(mx, __shfl_xor_sync(0xffffffffu, mx, o));
        float sum = 0.f;
        #pragma unroll
        for (int t = 0; t < 32; t++) {
            float e = __expf(mv[t] - mx);
            mv[t] = e;
            sum += e;
        }
        #pragma unroll
        for (int o = 16; o > 0; o >>= 1)
            sum += __shfl_xor_sync(0xffffffffu, sum, o);
        float inv = 1.f / sum;
        #pragma unroll
        for (int t = 0; t < 32; t++) As[(t * 32 + lane) * 8 + w] = mv[t] * inv;
    } else {
        float mv[16];
        float mx = -3.4e38f;
        #pragma unroll
        for (int t = 0; t < 16; t++) {
            float v = -srow[t * 32 + lane];
            mv[t] = v;
            mx = fmaxf(mx, v);
        }
        #pragma unroll
        for (int o = 16; o > 0; o >>= 1)
            mx = fmaxf(mx, __shfl_xor_sync(0xffffffffu, mx, o));
        float sum = 0.f;
        #pragma unroll
        for (int t = 0; t < 16; t++) {
            float e = __expf(mv[t] - mx);
            mv[t] = e;
            sum += e;
        }
        #pragma unroll
        for (int o = 16; o > 0; o >>= 1)
            sum += __shfl_xor_sync(0xffffffffu, sum, o);
        float inv = 1.f / sum;
        #pragma unroll
        for (int t = 0; t < 16; t++) As[(t * 32 + lane) * 8 + w] = mv[t] * inv;
    }
    __syncthreads();

    // ---- GEMM phase: cg = 4 cols, ks = K/8 slice ----
    int cg = tid & 31, ks = tid >> 5;
    int steps = K >> 3;
    int kstart = ks * steps;
    float4 acc4[8];
    #pragma unroll
    for (int r = 0; r < 8; r++) acc4[r] = make_float4(0.f, 0.f, 0.f, 0.f);
    const float4* As4 = (const float4*)As;
    const float4* B4 = (const float4*)B;
    #pragma unroll 2
    for (int kk = 0; kk < steps; kk++) {
        int k = kstart + kk;
        float4 a0 = As4[k * 2 + 0];      // rows 0-3 weights
        float4 a1 = As4[k * 2 + 1];      // rows 4-7 weights
        float4 b = B4[(size_t)k * 32 + cg];
        acc4[0].x = fmaf(a0.x, b.x, acc4[0].x); acc4[0].y = fmaf(a0.x, b.y, acc4[0].y);
        acc4[0].z = fmaf(a0.x, b.z, acc4[0].z); acc4[0].w = fmaf(a0.x, b.w, acc4[0].w);
        acc4[1].x = fmaf(a0.y, b.x, acc4[1].x); acc4[1].y = fmaf(a0.y, b.y, acc4[1].y);
        acc4[1].z = fmaf(a0.y, b.z, acc4[1].z); acc4[1].w = fmaf(a0.y, b.w, acc4[1].w);
        acc4[2].x = fmaf(a0.z, b.x, acc4[2].x); acc4[2].y = fmaf(a0.z, b.y, acc4[2].y);
        acc4[2].z = fmaf(a0.z, b.z, acc4[2].z); acc4[2].w = fmaf(a0.z, b.w, acc4[2].w);
        acc4[3].x = fmaf(a0.w, b.x, acc4[3].x); acc4[3].y = fmaf(a0.w, b.y, acc4[3].y);
        acc4[3].z = fmaf(a0.w, b.z, acc4[3].z); acc4[3].w = fmaf(a0.w, b.w, acc4[3].w);
        acc4[4].x = fmaf(a1.x, b.x, acc4[4].x); acc4[4].y = fmaf(a1.x, b.y, acc4[4].y);
        acc4[4].z = fmaf(a1.x, b.z, acc4[4].z); acc4[4].w = fmaf(a1.x, b.w, acc4[4].w);
        acc4[5].x = fmaf(a1.y, b.x, acc4[5].x); acc4[5].y = fmaf(a1.y, b.y, acc4[5].y);
        acc4[5].z = fmaf(a1.y, b.z, acc4[5].z); acc4[5].w = fmaf(a1.y, b.w, acc4[5].w);
        acc4[6].x = fmaf(a1.z, b.x, acc4[6].x); acc4[6].y = fmaf(a1.z, b.y, acc4[6].y);
        acc4[6].z = fmaf(a1.z, b.z, acc4[6].z); acc4[6].w = fmaf(a1.z, b.w, acc4[6].w);
        acc4[7].x = fmaf(a1.w, b.x, acc4[7].x); acc4[7].y = fmaf(a1.w, b.y, acc4[7].y);
        acc4[7].z = fmaf(a1.w, b.z, acc4[7].z); acc4[7].w = fmaf(a1.w, b.w, acc4[7].w);
    }
    __syncthreads();   // all As reads done before overwrite
    float4* P4 = (float4*)As;
    #pragma unroll
    for (int r = 0; r < 8; r++) P4[ks * 256 + r * 32 + cg] = acc4[r];
    __syncthreads();
    // reduction: thread tid sums one float4 over 8 slices
    float4 s = P4[tid];
    #pragma unroll
    for (int sl = 1; sl < 8; sl++) {
        float4 p = P4[sl * 256 + tid];
        s.x += p.x; s.y += p.y; s.z += p.z; s.w += p.w;
    }
    int r = tid >> 5, cc = tid & 31;
    ((float4*)(Y + (size_t)(r0 + r) * 128))[cc] = s;
}

// ---------------- gate: 48 blocks x 256 (2 subtiles of 16 rows) ----------------
__global__ void __launch_bounds__(256) k_gate(const float* __restrict__ lig,
                                              const float* __restrict__ poc,
                                              const float* __restrict__ aggl,
                                              const float* __restrict__ aggp,
                                              const float* __restrict__ Wgl,
                                              const float* __restrict__ bgl,
                                              const float* __restrict__ Wgp,
                                              const float* __restrict__ bgp,
                                              float* __restrict__ lige,
                                              float* __restrict__ poce) {
    __shared__ __align__(16) float smem[2 * 4096];
    int tid = threadIdx.x;
    int sub = tid >> 7, st = tid & 127;
    int vb = blockIdx.x * 2 + sub;
    float* xs = smem + sub * 4096;
    float* as_ = xs + 2048;
    const float* X; const float* A; const float* W; const float* B;
    float* Y; int r0;
    if (vb < 32) { X = lig; A = aggl; W = Wgl; B = bgl; Y = lige; r0 = vb * 16; }
    else { X = poc; A = aggp; W = Wgp; B = bgp; Y = poce; r0 = (vb - 32) * 16; }
    for (int idx = st; idx < 512; idx += 128) {
        ((float4*)xs)[idx] = ((const float4*)(X + (size_t)r0 * 128))[idx];
        ((float4*)as_)[idx] = ((const float4*)(A + (size_t)r0 * 128))[idx];
    }
    __syncthreads();
    const float4* Xs4 = (const float4*)xs;
    const float4* As4 = (const float4*)as_;
    float acc[16];
    float bv = B[st];
    #pragma unroll
    for (int r = 0; r < 16; r++) acc[r] = bv;
    const float4* w4 = (const float4*)(W + (size_t)st * 256);
    #pragma unroll 2
    for (int kb = 0; kb < 32; kb++) {
        float4 wv = w4[kb];
        #pragma unroll
        for (int r = 0; r < 16; r++) {
            float4 x = Xs4[r * 32 + kb];
            acc[r] = fmaf(x.x, wv.x, acc[r]);
            acc[r] = fmaf(x.y, wv.y, acc[r]);
            acc[r] = fmaf(x.z, wv.z, acc[r]);
            acc[r] = fmaf(x.w, wv.w, acc[r]);
        }
    }
    #pragma unroll 2
    for (int kb = 0; kb < 32; kb++) {
        float4 wv = w4[32 + kb];
        #pragma unroll
        for (int r = 0; r < 16; r++) {
            float4 x = As4[r * 32 + kb];
            acc[r] = fmaf(x.x, wv.x, acc[r]);
            acc[r] = fmaf(x.y, wv.y, acc[r]);
            acc[r] = fmaf(x.z, wv.z, acc[r]);
            acc[r] = fmaf(x.w, wv.w, acc[r]);
        }
    }
    #pragma unroll
    for (int r = 0; r < 16; r++) {
        float g = 1.f / (1.f + __expf(-acc[r]));
        float xv = xs[r * 128 + st], av = as_[r * 128 + st];
        Y[(size_t)(r0 + r) * 128 + st] = g * xv + (1.f - g) * av;
    }
}

// ---------------- qkv: 144 blocks x 256 (288 subtiles of 16 rows x 128 cols) --
__global__ void __launch_bounds__(256) k_qkv(const float* __restrict__ lige,
                                             const float* __restrict__ poce,
                                             const float* __restrict__ W,
                                             const float* __restrict__ B,
                                             float* __restrict__ qkvl,
                                             float* __restrict__ qkvp) {
    __shared__ __align__(16) float smem[2 * 2048];
    int tid = threadIdx.x;
    int sub = tid >> 7, st = tid & 127;
    int vb = blockIdx.x * 2 + sub;
    float* Xs = smem + sub * 2048;
    int p = vb / 96, tile = vb % 96;
    const float* X; float* Y; int r0;
    if (tile < 32) { X = lige; Y = qkvl; r0 = tile * 16; }
    else           { X = poce; Y = qkvp; r0 = (tile - 32) * 16; }
    for (int idx = st; idx < 512; idx += 128)
        ((float4*)Xs)[idx] = ((const float4*)(X + (size_t)r0 * 128))[idx];
    __syncthreads();
    const float4* Xs4 = (const float4*)Xs;
    int c = p * 128 + st;
    float acc[16];
    float bv = B[c];
    #pragma unroll
    for (int r = 0; r < 16; r++) acc[r] = bv;
    const float4* w4 = (const float4*)(W + (size_t)c * 128);
    #pragma unroll 2
    for (int kb = 0; kb < 32; kb++) {
        float4 wv = w4[kb];
        #pragma unroll
        for (int r = 0; r < 16; r++) {
            float4 x = Xs4[r * 32 + kb];
            acc[r] = fmaf(x.x, wv.x, acc[r]);
            acc[r] = fmaf(x.y, wv.y, acc[r]);
            acc[r] = fmaf(x.z, wv.z, acc[r]);
            acc[r] = fmaf(x.w, wv.w, acc[r]);
        }
    }
    #pragma unroll
    for (int r = 0; r < 16; r++) Y[(size_t)(r0 + r) * 384 + c] = acc[r];
}

// ---------------- merged flash attention (both directions) --------------------
// grid(96, 8), block 512: warp-per-query, online softmax, hd=16.
__global__ void __launch_bounds__(512) k_flash2(const float* __restrict__ qkvl,
                                                const float* __restrict__ qkvp,
                                                float* __restrict__ attl,
                                                float* __restrict__ attp) {
    __shared__ __align__(16) float4 Ks[128 * 5];
    __shared__ __align__(16) float4 Vs[128 * 5];
    int bx = blockIdx.x, h = blockIdx.y;
    int tid = threadIdx.x;
    int w = tid >> 5, lane = tid & 31;
    const float* Qb; const float* KVb; float* outp; int nk, i;
    if (bx < 32) { Qb = qkvl; KVb = qkvp; outp = attl; nk = 1024; i = bx * 16 + w; }
    else         { Qb = qkvp; KVb = qkvl; outp = attp; nk = 512; i = (bx - 32) * 16 + w; }

    const float* qp = Qb + (size_t)i * 384 + h * 16;
    float4 q0 = ((const float4*)qp)[0];
    float4 q1 = ((const float4*)qp)[1];
    float4 q2 = ((const float4*)qp)[2];
    float4 q3 = ((const float4*)qp)[3];

    float m = -3.4e38f, l = 0.f;
    float acc[16];
    #pragma unroll
    for (int d = 0; d < 16; d++) acc[d] = 0.f;

    int jload = tid >> 2, cload = tid & 3;
    const float* kbase = KVb + (size_t)jload * 384 + 128 + h * 16 + cload * 4;

    for (int jb = 0; jb < nk; jb += 128) {
        __syncthreads();
        Ks[jload * 5 + cload] = *(const float4*)(kbase + (size_t)jb * 384);
        Vs[jload * 5 + cload] = *(const float4*)(kbase + (size_t)jb * 384 + 128);
        __syncthreads();

        float s[4];
        #pragma unroll
        for (int jj = 0; jj < 4; jj++) {
            const float4* kr = Ks + (jj * 32 + lane) * 5;
            float4 k0 = kr[0], k1 = kr[1], k2 = kr[2], k3 = kr[3];
            float t = q0.x * k0.x;
            t = fmaf(q0.y, k0.y, t); t = fmaf(q0.z, k0.z, t); t = fmaf(q0.w, k0.w, t);
            t = fmaf(q1.x, k1.x, t); t = fmaf(q1.y, k1.y, t);
            t = fmaf(q1.z, k1.z, t); t = fmaf(q1.w, k1.w, t);
            t = fmaf(q2.x, k2.x, t); t = fmaf(q2.y, k2.y, t);
            t = fmaf(q2.z, k2.z, t); t = fmaf(q2.w, k2.w, t);
            t = fmaf(q3.x, k3.x, t); t = fmaf(q3.y, k3.y, t);
            t = fmaf(q3.z, k3.z, t); t = fmaf(q3.w, k3.w, t);
            s[jj] = t * 0.25f;
        }
        float tmax = fmaxf(fmaxf(s[0], s[1]), fmaxf(s[2], s[3]));
        #pragma unroll
        for (int o = 16; o > 0; o >>= 1)
            tmax = fmaxf(tmax, __shfl_xor_sync(0xffffffffu, tmax, o));
        float mnew = fmaxf(m, tmax);
        float corr = __expf(m - mnew);
        m = mnew;
        l *= corr;
        #pragma unroll
        for (int d = 0; d < 16; d++) acc[d] *= corr;
        #pragma unroll
        for (int jj = 0; jj < 4; jj++) {
            float p = __expf(s[jj] - m);
            l += p;
            const float4* vr = Vs + (jj * 32 + lane) * 5;
            float4 v0 = vr[0], v1 = vr[1], v2 = vr[2], v3 = vr[3];
            acc[0]  = fmaf(p, v0.x, acc[0]);  acc[1]  = fmaf(p, v0.y, acc[1]);
            acc[2]  = fmaf(p, v0.z, acc[2]);  acc[3]  = fmaf(p, v0.w, acc[3]);
            acc[4]  = fmaf(p, v1.x, acc[4]);  acc[5]  = fmaf(p, v1.y, acc[5]);
            acc[6]  = fmaf(p, v1.z, acc[6]);  acc[7]  = fmaf(p, v1.w, acc[7]);
            acc[8]  = fmaf(p, v2.x, acc[8]);  acc[9]  = fmaf(p, v2.y, acc[9]);
            acc[10] = fmaf(p, v2.z, acc[10]); acc[11] = fmaf(p, v2.w, acc[11]);
            acc[12] = fmaf(p, v3.x, acc[12]); acc[13] = fmaf(p, v3.y, acc[13]);
            acc[14] = fmaf(p, v3.z, acc[14]); acc[15] = fmaf(p, v3.w, acc[15]);
        }
    }

    #pragma unroll
    for (int o = 16; o > 0; o >>= 1) l += __shfl_xor_sync(0xffffffffu, l, o);
    #pragma unroll
    for (int d = 0; d < 16; d++) {
        #pragma unroll
        for (int o = 16; o > 0; o >>= 1)
            acc[d] += __shfl_xor_sync(0xffffffffu, acc[d], o);
    }
    float val = 0.f;
    #pragma unroll
    for (int d = 0; d < 16; d++) if (lane == d) val = acc[d];
    if (lane < 16) outp[(size_t)i * 128 + h * 16 + lane] = val * (1.f / l);
}

// ---------------- out-proj + residual + LN: 48 blocks x 256 (2 subtiles) ------
__global__ void __launch_bounds__(256) k_outln(const float* __restrict__ attl,
                                               const float* __restrict__ attp,
                                               const float* __restrict__ W,
                                               const float* __restrict__ bias,
                                               const float* __restrict__ lige,
                                               const float* __restrict__ poce,
                                               const float* __restrict__ g_l,
                                               const float* __restrict__ be_l,
                                               const float* __restrict__ g_p,
                                               const float* __restrict__ be_p,
                                               float* __restrict__ out) {
    __shared__ __align__(16) float smem[2 * 4160];
    int tid = threadIdx.x;
    int sub = tid >> 7, st = tid & 127;
    int vb = blockIdx.x * 2 + sub;
    float* Xs = smem + sub * 4160;
    float* T = Xs + 2048;
    float* mu = T + 2048;     // 16
    float* iv = mu + 16;      // 16
    const float* X; const float* R; const float* gg; const float* bb;
    float* O; int r0;
    if (vb < 32) { X = attl; R = lige; gg = g_l; bb = be_l; O = out; r0 = vb * 16; }
    else {
        X = attp; R = poce; gg = g_p; bb = be_p;
        O = out + 512 * 128; r0 = (vb - 32) * 16;
    }
    for (int idx = st; idx < 512; idx += 128)
        ((float4*)Xs)[idx] = ((const float4*)(X + (size_t)r0 * 128))[idx];
    __syncthreads();
    const float4* Xs4 = (const float4*)Xs;
    float acc[16];
    float bv = bias[st];
    #pragma unroll
    for (int r = 0; r < 16; r++) acc[r] = bv;
    const float4* w4 = (const float4*)(W + (size_t)st * 128);
    #pragma unroll 2
    for (int kb = 0; kb < 32; kb++) {
        float4 wv = w4[kb];
        #pragma unroll
        for (int r = 0; r < 16; r++) {
            float4 x = Xs4[r * 32 + kb];
            acc[r] = fmaf(x.x, wv.x, acc[r]);
            acc[r] = fmaf(x.y, wv.y, acc[r]);
            acc[r] = fmaf(x.z, wv.z, acc[r]);
            acc[r] = fmaf(x.w, wv.w, acc[r]);
        }
    }
    #pragma unroll
    for (int r = 0; r < 16; r++)
        T[r * 128 + st] = acc[r] + R[(size_t)(r0 + r) * 128 + st];
    __syncthreads();

    int wrp = st >> 5, lane = st & 31;
    #pragma unroll
    for (int rr = 0; rr < 4; rr++) {
        int r = wrp * 4 + rr;
        float t0 = T[r * 128 + lane], t1 = T[r * 128 + lane + 32];
        float t2 = T[r * 128 + lane + 64], t3 = T[r * 128 + lane + 96];
        float s = (t0 + t1) + (t2 + t3);
        #pragma unroll
        for (int o = 16; o > 0; o >>= 1) s += __shfl_xor_sync(0xffffffffu, s, o);
        float mean = s * (1.f / 128.f);
        float d0 = t0 - mean, d1 = t1 - mean, d2 = t2 - mean, d3 = t3 - mean;
        float v = (d0 * d0 + d1 * d1) + (d2 * d2 + d3 * d3);
        #pragma unroll
        for (int o = 16; o > 0; o >>= 1) v += __shfl_xor_sync(0xffffffffu, v, o);
        if (lane == 0) {
            mu[r] = mean;
            iv[r] = rsqrtf(v * (1.f / 128.f) + 1e-5f);
        }
    }
    __syncthreads();
    float gc = gg[st], bc = bb[st];
    #pragma unroll
    for (int r = 0; r < 16; r++) {
        float t = T[r * 128 + st];
        O[(size_t)(r0 + r) * 128 + st] = (t - mu[r]) * iv[r] * gc + bc;
    }
}

// ---------------- launch ------------------------------------------------------
extern "C" void kernel_launch(void* const* d_in, const int* in_sizes, int n_in,
                              void* d_out, int out_size) {
    const float* lf   = (const float*)d_in[0];
    const float* pf   = (const float*)d_in[1];
    const float* lc   = (const float*)d_in[2];
    const float* pc   = (const float*)d_in[3];
    const float* Wl   = (const float*)d_in[4];
    const float* bl   = (const float*)d_in[5];
    const float* Wp   = (const float*)d_in[6];
    const float* bp   = (const float*)d_in[7];
    const float* Wd1  = (const float*)d_in[8];
    const float* bd1  = (const float*)d_in[9];
    const float* Wd2  = (const float*)d_in[10];
    const float* bd2  = (const float*)d_in[11];
    const float* Wd3  = (const float*)d_in[12];
    const float* bd3  = (const float*)d_in[13];
    const float* Wgl  = (const float*)d_in[14];
    const float* bgl  = (const float*)d_in[15];
    const float* Wgp  = (const float*)d_in[16];
    const float* bgp  = (const float*)d_in[17];
    const float* Wqkv = (const float*)d_in[18];
    const float* bqkv = (const float*)d_in[19];
    const float* Wo   = (const float*)d_in[20];
    const float* bo   = (const float*)d_in[21];
    const float* g_l  = (const float*)d_in[22];
    const float* be_l = (const float*)d_in[23];
    const float* g_p  = (const float*)d_in[24];
    const float* be_p = (const float*)d_in[25];
    float* out = (float*)d_out;

    float* SB = nullptr;
    cudaGetSymbolAddress((void**)&SB, g_scratch);
    float* s_lig  = SB + OFF_LIG;
    float* s_poc  = SB + OFF_POC;
    float* s_m    = SB + OFF_M;
    float* s_mt   = SB + OFF_MT;
    float* s_aggl = SB + OFF_AGGL;
    float* s_aggp = SB + OFF_AGGP;
    float* s_lige = SB + OFF_LIGE;
    float* s_poce = SB + OFF_POCE;
    float* s_qkvl = SB + OFF_QKVL;
    float* s_qkvp = SB + OFF_QKVP;
    float* s_attl = SB + OFF_ATTL;
    float* s_attp = SB + OFF_ATTP;
    float* s_tab  = SB + OFF_TAB;

    k_pre<<<64, 256>>>(Wd1, bd1, Wd2, bd2, Wd3, bd3, s_tab,
                       lf, pf, Wl, bl, Wp, bp, s_lig, s_poc);
    k_pairm<<<128, 256>>>(lc, pc, s_tab, s_m, s_mt);
    k_aggsoft<<<192, 256>>>(s_m, s_mt, s_poc, s_lig, s_aggl, s_aggp);
    k_gate<<<48, 256>>>(s_lig, s_poc, s_aggl, s_aggp, Wgl, bgl, Wgp, bgp,
                        s_lige, s_poce);
    k_qkv<<<144, 256>>>(s_lige, s_poce, Wqkv, bqkv, s_qkvl, s_qkvp);
    k_flash2<<<dim3(96, 8), 512>>>(s_qkvl, s_qkvp, s_attl, s_attp);
    k_outln<<<48, 256>>>(s_attl, s_attp, Wo, bo, s_lige, s_poce,
                         g_l, be_l, g_p, be_p, out);
}

// round 11
// speedup vs baseline: 1.5857x; 1.0497x over previous
#include <cuda_runtime.h>
#include <math.h>

// ---------------- scratch (device globals; no allocation allowed) ----------
#define OFF_LIG     0           // 512*128
#define OFF_POC     65536       // 1024*128
#define OFF_M       196608      // 512*1024
#define OFF_MT      720896      // 1024*512
#define OFF_AGGL    1245184     // 512*128
#define OFF_AGGP    1310720     // 1024*128
#define OFF_LIGE    1441792     // 512*128
#define OFF_POCE    1507328     // 1024*128
#define OFF_QKVL    1638400     // 512*384
#define OFF_QKVP    1835008     // 1024*384
#define OFF_ATTL    2228224     // 512*128
#define OFF_ATTP    2293760     // 1024*128
#define OFF_TAB     2424832     // 4096
#define SCRATCH_FLOATS 2428928

__device__ float g_scratch[SCRATCH_FLOATS];

#define TAB_N 4096
#define D_MAX 35.0f

// ---------------- k_pre: 112 blocks x 256 (2 subtiles).
// subs 0..31: distance table slices. subs 32..223: 8-row input-proj tiles. ----
__global__ void __launch_bounds__(256) k_pre(const float* __restrict__ Wd1,
                                             const float* __restrict__ bd1,
                                             const float* __restrict__ Wd2,
                                             const float* __restrict__ bd2,
                                             const float* __restrict__ Wd3,
                                             const float* __restrict__ bd3,
                                             float* __restrict__ tab,
                                             const float* __restrict__ lf,
                                             const float* __restrict__ pf,
                                             const float* __restrict__ Wl,
                                             const float* __restrict__ bl,
                                             const float* __restrict__ Wp,
                                             const float* __restrict__ bp,
                                             float* __restrict__ lig,
                                             float* __restrict__ poc) {
    __shared__ __align__(16) float smem[2 * 2304];
    int tid = threadIdx.x;
    int sub = tid >> 7, st = tid & 127;
    int vb = blockIdx.x * 2 + sub;
    float* sbuf = smem + sub * 2304;          // 2048 data
    float* w1s = sbuf + 2048;                 // 32
    float* b1s = w1s + 32;                    // 32
    float* b2s = b1s + 32;                    // 64
    float* wms = b2s + 64;                    // 64
    float* mcs = wms + 64;                    // 1

    if (vb < 32) {
        // ---- table slice ----
        for (int idx = st; idx < 2048; idx += 128) sbuf[idx] = Wd2[idx];
        if (st < 32) { w1s[st] = Wd1[st]; b1s[st] = bd1[st]; }
        if (st >= 32 && st < 96) b2s[st - 32] = bd2[st - 32];
        if (st < 64) {
            float s = 0.f;
            for (int i = 0; i < 128; i++) s += Wd3[i * 64 + st];
            wms[st] = s * (1.f / 128.f);
        }
        if (st == 127) {
            float s = 0.f;
            for (int i = 0; i < 128; i++) s += bd3[i];
            *mcs = s * (1.f / 128.f);
        }
        __syncthreads();
        int idx = vb * 128 + st;
        float d = (float)idx * (D_MAX / (float)(TAB_N - 1));
        float h1[32];
        #pragma unroll
        for (int k = 0; k < 32; k++) h1[k] = fmaxf(fmaf(d, w1s[k], b1s[k]), 0.f);
        float mval = *mcs;
        #pragma unroll 1
        for (int j = 0; j < 64; j++) {
            const float4* wr = (const float4*)(sbuf + j * 32);
            float a0 = 0.f, a1 = 0.f, a2 = 0.f, a3 = 0.f;
            #pragma unroll
            for (int q = 0; q < 8; q++) {
                float4 w = wr[q];
                a0 = fmaf(w.x, h1[4 * q + 0], a0);
                a1 = fmaf(w.y, h1[4 * q + 1], a1);
                a2 = fmaf(w.z, h1[4 * q + 2], a2);
                a3 = fmaf(w.w, h1[4 * q + 3], a3);
            }
            float pre = b2s[j] + ((a0 + a1) + (a2 + a3));
            mval = fmaf(fmaxf(pre, 0.f), wms[j], mval);
        }
        tab[idx] = mval;
    } else {
        __syncthreads();  // match table path's barrier (same block)
        // ---- input projection: 8 rows, float4-k blocked ----
        int pb = vb - 32;                   // 0..191
        const float* X; const float* W; const float* B; float* Y; int r0;
        if (pb < 64) { X = lf; W = Wl; B = bl; Y = lig; r0 = pb * 8; }
        else         { X = pf; W = Wp; B = bp; Y = poc; r0 = (pb - 64) * 8; }
        const float4* xsrc = (const float4*)(X + (size_t)r0 * 128);
        for (int idx = st; idx < 256; idx += 128) ((float4*)sbuf)[idx] = xsrc[idx];
        __syncthreads();
        const float4* Xs4 = (const float4*)sbuf;
        float acc[8];
        float bv = B[st];
        #pragma unroll
        for (int r = 0; r < 8; r++) acc[r] = bv;
        const float4* w4 = (const float4*)(W + (size_t)st * 128);
        #pragma unroll 4
        for (int kb = 0; kb < 32; kb++) {
            float4 wv = w4[kb];
            #pragma unroll
            for (int r = 0; r < 8; r++) {
                float4 x = Xs4[r * 32 + kb];
                acc[r] = fmaf(x.x, wv.x, acc[r]);
                acc[r] = fmaf(x.y, wv.y, acc[r]);
                acc[r] = fmaf(x.z, wv.z, acc[r]);
                acc[r] = fmaf(x.w, wv.w, acc[r]);
            }
        }
        #pragma unroll
        for (int r = 0; r < 8; r++) Y[(size_t)(r0 + r) * 128 + st] = acc[r];
    }
}

// ---------------- pair: m via table lerp, write M and MT ----------------------
// grid 128 (4 lig rows each), block 256.
__global__ void __launch_bounds__(256) k_pairm(const float* __restrict__ lc,
                                               const float* __restrict__ pc,
                                               const float* __restrict__ tab,
                                               float* __restrict__ M,
                                               float* __restrict__ MT) {
    __shared__ float tabs[TAB_N];
    __shared__ float pcs[3072];
    int tid = threadIdx.x;
    for (int idx = tid; idx < TAB_N; idx += 256) tabs[idx] = tab[idx];
    for (int idx = tid; idx < 3072; idx += 256) pcs[idx] = pc[idx];
    __syncthreads();

    int i0 = blockIdx.x * 4;
    float lx[4], ly[4], lz[4];
    #pragma unroll
    for (int r = 0; r < 4; r++) {
        lx[r] = lc[(i0 + r) * 3 + 0];
        ly[r] = lc[(i0 + r) * 3 + 1];
        lz[r] = lc[(i0 + r) * 3 + 2];
    }
    const float invh = (float)(TAB_N - 1) / D_MAX;
    #pragma unroll
    for (int jj = 0; jj < 4; jj++) {
        int j = jj * 256 + tid;
        float px = pcs[j * 3 + 0], py = pcs[j * 3 + 1], pz = pcs[j * 3 + 2];
        float4 v;
        float* vp = (float*)&v;
        #pragma unroll
        for (int r = 0; r < 4; r++) {
            float dx = lx[r] - px, dy = ly[r] - py, dz = lz[r] - pz;
            float d = sqrtf(fmaf(dx, dx, fmaf(dy, dy, dz * dz)));
            float t = d * invh;
            int t0 = min((int)t, TAB_N - 2);
            float f = t - (float)t0;
            float v0 = tabs[t0], v1 = tabs[t0 + 1];
            vp[r] = fmaf(f, v1 - v0, v0);
            M[(size_t)(i0 + r) * 1024 + j] = vp[r];
        }
        *(float4*)(MT + (size_t)j * 512 + i0) = v;
    }
}

// ---------------- agg with fused softmax, register-blocked GEMM ---------------
// grid 192, block 256. 8 rows/tile.
__global__ void __launch_bounds__(256) k_aggsoft(const float* __restrict__ M,
                                                 const float* __restrict__ MT,
                                                 const float* __restrict__ poc,
                                                 const float* __restrict__ lig,
                                                 float* __restrict__ aggl,
                                                 float* __restrict__ aggp) {
    __shared__ __align__(16) float As[8192];
    int tid = threadIdx.x, bx = blockIdx.x;
    const float* S; const float* B; float* Y; int r0, K;
    if (bx < 64) { S = M;  B = poc; Y = aggl; r0 = bx * 8;        K = 1024; }
    else         { S = MT; B = lig; Y = aggp; r0 = (bx - 64) * 8; K = 512;  }

    // ---- softmax phase: warp per row, fully unrolled ----
    int w = tid >> 5, lane = tid & 31;
    const float* srow = S + (size_t)(r0 + w) * K;
    if (K == 1024) {
        float mv[32];
        float mx = -3.4e38f;
        #pragma unroll
        for (int t = 0; t < 32; t++) {
            float v = -srow[t * 32 + lane];
            mv[t] = v;
            mx = fmaxf(mx, v);
        }
        #pragma unroll
        for (int o = 16; o > 0; o >>= 1)
            mx = fmaxf(mx, __shfl_xor_sync(0xffffffffu, mx, o));
        float sum = 0.f;
        #pragma unroll
        for (int t = 0; t < 32; t++) {
            float e = __expf(mv[t] - mx);
            mv[t] = e;
            sum += e;
        }
        #pragma unroll
        for (int o = 16; o > 0; o >>= 1)
            sum += __shfl_xor_sync(0xffffffffu, sum, o);
        float inv = 1.f / sum;
        #pragma unroll
        for (int t = 0; t < 32; t++) As[(t * 32 + lane) * 8 + w] = mv[t] * inv;
    } else {
        float mv[16];
        float mx = -3.4e38f;
        #pragma unroll
        for (int t = 0; t < 16; t++) {
            float v = -srow[t * 32 + lane];
            mv[t] = v;
            mx = fmaxf(mx, v);
        }
        #pragma unroll
        for (int o = 16; o > 0; o >>= 1)
            mx = fmaxf(mx, __shfl_xor_sync(0xffffffffu, mx, o));
        float sum = 0.f;
        #pragma unroll
        for (int t = 0; t < 16; t++) {
            float e = __expf(mv[t] - mx);
            mv[t] = e;
            sum += e;
        }
        #pragma unroll
        for (int o = 16; o > 0; o >>= 1)
            sum += __shfl_xor_sync(0xffffffffu, sum, o);
        float inv = 1.f / sum;
        #pragma unroll
        for (int t = 0; t < 16; t++) As[(t * 32 + lane) * 8 + w] = mv[t] * inv;
    }
    __syncthreads();

    // ---- GEMM phase: cg = 4 cols, ks = K/8 slice ----
    int cg = tid & 31, ks = tid >> 5;
    int steps = K >> 3;
    int kstart = ks * steps;
    float4 acc4[8];
    #pragma unroll
    for (int r = 0; r < 8; r++) acc4[r] = make_float4(0.f, 0.f, 0.f, 0.f);
    const float4* As4 = (const float4*)As;
    const float4* B4 = (const float4*)B;
    #pragma unroll 2
    for (int kk = 0; kk < steps; kk++) {
        int k = kstart + kk;
        float4 a0 = As4[k * 2 + 0];
        float4 a1 = As4[k * 2 + 1];
        float4 b = B4[(size_t)k * 32 + cg];
        acc4[0].x = fmaf(a0.x, b.x, acc4[0].x); acc4[0].y = fmaf(a0.x, b.y, acc4[0].y);
        acc4[0].z = fmaf(a0.x, b.z, acc4[0].z); acc4[0].w = fmaf(a0.x, b.w, acc4[0].w);
        acc4[1].x = fmaf(a0.y, b.x, acc4[1].x); acc4[1].y = fmaf(a0.y, b.y, acc4[1].y);
        acc4[1].z = fmaf(a0.y, b.z, acc4[1].z); acc4[1].w = fmaf(a0.y, b.w, acc4[1].w);
        acc4[2].x = fmaf(a0.z, b.x, acc4[2].x); acc4[2].y = fmaf(a0.z, b.y, acc4[2].y);
        acc4[2].z = fmaf(a0.z, b.z, acc4[2].z); acc4[2].w = fmaf(a0.z, b.w, acc4[2].w);
        acc4[3].x = fmaf(a0.w, b.x, acc4[3].x); acc4[3].y = fmaf(a0.w, b.y, acc4[3].y);
        acc4[3].z = fmaf(a0.w, b.z, acc4[3].z); acc4[3].w = fmaf(a0.w, b.w, acc4[3].w);
        acc4[4].x = fmaf(a1.x, b.x, acc4[4].x); acc4[4].y = fmaf(a1.x, b.y, acc4[4].y);
        acc4[4].z = fmaf(a1.x, b.z, acc4[4].z); acc4[4].w = fmaf(a1.x, b.w, acc4[4].w);
        acc4[5].x = fmaf(a1.y, b.x, acc4[5].x); acc4[5].y = fmaf(a1.y, b.y, acc4[5].y);
        acc4[5].z = fmaf(a1.y, b.z, acc4[5].z); acc4[5].w = fmaf(a1.y, b.w, acc4[5].w);
        acc4[6].x = fmaf(a1.z, b.x, acc4[6].x); acc4[6].y = fmaf(a1.z, b.y, acc4[6].y);
        acc4[6].z = fmaf(a1.z, b.z, acc4[6].z); acc4[6].w = fmaf(a1.z, b.w, acc4[6].w);
        acc4[7].x = fmaf(a1.w, b.x, acc4[7].x); acc4[7].y = fmaf(a1.w, b.y, acc4[7].y);
        acc4[7].z = fmaf(a1.w, b.z, acc4[7].z); acc4[7].w = fmaf(a1.w, b.w, acc4[7].w);
    }
    __syncthreads();
    float4* P4 = (float4*)As;
    #pragma unroll
    for (int r = 0; r < 8; r++) P4[ks * 256 + r * 32 + cg] = acc4[r];
    __syncthreads();
    float4 s = P4[tid];
    #pragma unroll
    for (int sl = 1; sl < 8; sl++) {
        float4 p = P4[sl * 256 + tid];
        s.x += p.x; s.y += p.y; s.z += p.z; s.w += p.w;
    }
    int r = tid >> 5, cc = tid & 31;
    ((float4*)(Y + (size_t)(r0 + r) * 128))[cc] = s;
}

// ---------------- gate: 192 blocks x 256, 8-row tiles, halves split K=256 -----
__global__ void __launch_bounds__(256) k_gate(const float* __restrict__ lig,
                                              const float* __restrict__ poc,
                                              const float* __restrict__ aggl,
                                              const float* __restrict__ aggp,
                                              const float* __restrict__ Wgl,
                                              const float* __restrict__ bgl,
                                              const float* __restrict__ Wgp,
                                              const float* __restrict__ bgp,
                                              float* __restrict__ lige,
                                              float* __restrict__ poce) {
    __shared__ __align__(16) float xs[1024];
    __shared__ __align__(16) float as_[1024];
    __shared__ __align__(16) float red[1024];
    int tid = threadIdx.x, vb = blockIdx.x;
    const float* X; const float* A; const float* W; const float* B;
    float* Y; int r0;
    if (vb < 64) { X = lig; A = aggl; W = Wgl; B = bgl; Y = lige; r0 = vb * 8; }
    else { X = poc; A = aggp; W = Wgp; B = bgp; Y = poce; r0 = (vb - 64) * 8; }
    ((float4*)xs)[tid] = ((const float4*)(X + (size_t)r0 * 128))[tid];
    ((float4*)as_)[tid] = ((const float4*)(A + (size_t)r0 * 128))[tid];
    __syncthreads();
    int c = tid & 127, part = tid >> 7;
    const float4* S4 = (const float4*)(part ? as_ : xs);
    float acc[8];
    float bv = part ? 0.f : B[c];
    #pragma unroll
    for (int r = 0; r < 8; r++) acc[r] = bv;
    const float4* w4 = (const float4*)(W + (size_t)c * 256 + part * 128);
    #pragma unroll 4
    for (int kb = 0; kb < 32; kb++) {
        float4 wv = w4[kb];
        #pragma unroll
        for (int r = 0; r < 8; r++) {
            float4 x = S4[r * 32 + kb];
            acc[r] = fmaf(x.x, wv.x, acc[r]);
            acc[r] = fmaf(x.y, wv.y, acc[r]);
            acc[r] = fmaf(x.z, wv.z, acc[r]);
            acc[r] = fmaf(x.w, wv.w, acc[r]);
        }
    }
    if (part) {
        #pragma unroll
        for (int r = 0; r < 8; r++) red[c * 8 + r] = acc[r];
    }
    __syncthreads();
    if (!part) {
        #pragma unroll
        for (int r = 0; r < 8; r++) {
            float t = acc[r] + red[c * 8 + r];
            float g = 1.f / (1.f + __expf(-t));
            float xv = xs[r * 128 + c], av = as_[r * 128 + c];
            Y[(size_t)(r0 + r) * 128 + c] = g * xv + (1.f - g) * av;
        }
    }
}

// ---------------- qkv: 288 blocks x 256 (576 subtiles of 8 rows x 128 cols) ---
__global__ void __launch_bounds__(256) k_qkv(const float* __restrict__ lige,
                                             const float* __restrict__ poce,
                                             const float* __restrict__ W,
                                             const float* __restrict__ B,
                                             float* __restrict__ qkvl,
                                             float* __restrict__ qkvp) {
    __shared__ __align__(16) float smem[2 * 1024];
    int tid = threadIdx.x;
    int sub = tid >> 7, st = tid & 127;
    int vb = blockIdx.x * 2 + sub;       // 0..575
    float* Xs = smem + sub * 1024;
    int p = vb / 192, tile = vb % 192;
    const float* X; float* Y; int r0;
    if (tile < 64) { X = lige; Y = qkvl; r0 = tile * 8; }
    else           { X = poce; Y = qkvp; r0 = (tile - 64) * 8; }
    for (int idx = st; idx < 256; idx += 128)
        ((float4*)Xs)[idx] = ((const float4*)(X + (size_t)r0 * 128))[idx];
    __syncthreads();
    const float4* Xs4 = (const float4*)Xs;
    int c = p * 128 + st;
    float acc[8];
    float bv = B[c];
    #pragma unroll
    for (int r = 0; r < 8; r++) acc[r] = bv;
    const float4* w4 = (const float4*)(W + (size_t)c * 128);
    #pragma unroll 4
    for (int kb = 0; kb < 32; kb++) {
        float4 wv = w4[kb];
        #pragma unroll
        for (int r = 0; r < 8; r++) {
            float4 x = Xs4[r * 32 + kb];
            acc[r] = fmaf(x.x, wv.x, acc[r]);
            acc[r] = fmaf(x.y, wv.y, acc[r]);
            acc[r] = fmaf(x.z, wv.z, acc[r]);
            acc[r] = fmaf(x.w, wv.w, acc[r]);
        }
    }
    #pragma unroll
    for (int r = 0; r < 8; r++) Y[(size_t)(r0 + r) * 384 + c] = acc[r];
}

// ---------------- merged flash attention (both directions) --------------------
// grid(96, 8), block 512: warp-per-query, online softmax, hd=16.
__global__ void __launch_bounds__(512) k_flash2(const float* __restrict__ qkvl,
                                                const float* __restrict__ qkvp,
                                                float* __restrict__ attl,
                                                float* __restrict__ attp) {
    __shared__ __align__(16) float4 Ks[128 * 5];
    __shared__ __align__(16) float4 Vs[128 * 5];
    int bx = blockIdx.x, h = blockIdx.y;
    int tid = threadIdx.x;
    int w = tid >> 5, lane = tid & 31;
    const float* Qb; const float* KVb; float* outp; int nk, i;
    if (bx < 32) { Qb = qkvl; KVb = qkvp; outp = attl; nk = 1024; i = bx * 16 + w; }
    else         { Qb = qkvp; KVb = qkvl; outp = attp; nk = 512; i = (bx - 32) * 16 + w; }

    const float* qp = Qb + (size_t)i * 384 + h * 16;
    float4 q0 = ((const float4*)qp)[0];
    float4 q1 = ((const float4*)qp)[1];
    float4 q2 = ((const float4*)qp)[2];
    float4 q3 = ((const float4*)qp)[3];

    float m = -3.4e38f, l = 0.f;
    float acc[16];
    #pragma unroll
    for (int d = 0; d < 16; d++) acc[d] = 0.f;

    int jload = tid >> 2, cload = tid & 3;
    const float* kbase = KVb + (size_t)jload * 384 + 128 + h * 16 + cload * 4;

    for (int jb = 0; jb < nk; jb += 128) {
        __syncthreads();
        Ks[jload * 5 + cload] = *(const float4*)(kbase + (size_t)jb * 384);
        Vs[jload * 5 + cload] = *(const float4*)(kbase + (size_t)jb * 384 + 128);
        __syncthreads();

        float s[4];
        #pragma unroll
        for (int jj = 0; jj < 4; jj++) {
            const float4* kr = Ks + (jj * 32 + lane) * 5;
            float4 k0 = kr[0], k1 = kr[1], k2 = kr[2], k3 = kr[3];
            float t = q0.x * k0.x;
            t = fmaf(q0.y, k0.y, t); t = fmaf(q0.z, k0.z, t); t = fmaf(q0.w, k0.w, t);
            t = fmaf(q1.x, k1.x, t); t = fmaf(q1.y, k1.y, t);
            t = fmaf(q1.z, k1.z, t); t = fmaf(q1.w, k1.w, t);
            t = fmaf(q2.x, k2.x, t); t = fmaf(q2.y, k2.y, t);
            t = fmaf(q2.z, k2.z, t); t = fmaf(q2.w, k2.w, t);
            t = fmaf(q3.x, k3.x, t); t = fmaf(q3.y, k3.y, t);
            t = fmaf(q3.z, k3.z, t); t = fmaf(q3.w, k3.w, t);
            s[jj] = t * 0.25f;
        }
        float tmax = fmaxf(fmaxf(s[0], s[1]), fmaxf(s[2], s[3]));
        #pragma unroll
        for (int o = 16; o > 0; o >>= 1)
            tmax = fmaxf(tmax, __shfl_xor_sync(0xffffffffu, tmax, o));
        float mnew = fmaxf(m, tmax);
        float corr = __expf(m - mnew);
        m = mnew;
        l *= corr;
        #pragma unroll
        for (int d = 0; d < 16; d++) acc[d] *= corr;
        #pragma unroll
        for (int jj = 0; jj < 4; jj++) {
            float p = __expf(s[jj] - m);
            l += p;
            const float4* vr = Vs + (jj * 32 + lane) * 5;
            float4 v0 = vr[0], v1 = vr[1], v2 = vr[2], v3 = vr[3];
            acc[0]  = fmaf(p, v0.x, acc[0]);  acc[1]  = fmaf(p, v0.y, acc[1]);
            acc[2]  = fmaf(p, v0.z, acc[2]);  acc[3]  = fmaf(p, v0.w, acc[3]);
            acc[4]  = fmaf(p, v1.x, acc[4]);  acc[5]  = fmaf(p, v1.y, acc[5]);
            acc[6]  = fmaf(p, v1.z, acc[6]);  acc[7]  = fmaf(p, v1.w, acc[7]);
            acc[8]  = fmaf(p, v2.x, acc[8]);  acc[9]  = fmaf(p, v2.y, acc[9]);
            acc[10] = fmaf(p, v2.z, acc[10]); acc[11] = fmaf(p, v2.w, acc[11]);
            acc[12] = fmaf(p, v3.x, acc[12]); acc[13] = fmaf(p, v3.y, acc[13]);
            acc[14] = fmaf(p, v3.z, acc[14]); acc[15] = fmaf(p, v3.w, acc[15]);
        }
    }

    #pragma unroll
    for (int o = 16; o > 0; o >>= 1) l += __shfl_xor_sync(0xffffffffu, l, o);
    #pragma unroll
    for (int d = 0; d < 16; d++) {
        #pragma unroll
        for (int o = 16; o > 0; o >>= 1)
            acc[d] += __shfl_xor_sync(0xffffffffu, acc[d], o);
    }
    float val = 0.f;
    #pragma unroll
    for (int d = 0; d < 16; d++) if (lane == d) val = acc[d];
    if (lane < 16) outp[(size_t)i * 128 + h * 16 + lane] = val * (1.f / l);
}

// ---------------- out-proj + residual + LN: 192 blocks x 128, 8-row tiles -----
__global__ void __launch_bounds__(128) k_outln(const float* __restrict__ attl,
                                               const float* __restrict__ attp,
                                               const float* __restrict__ W,
                                               const float* __restrict__ bias,
                                               const float* __restrict__ lige,
                                               const float* __restrict__ poce,
                                               const float* __restrict__ g_l,
                                               const float* __restrict__ be_l,
                                               const float* __restrict__ g_p,
                                               const float* __restrict__ be_p,
                                               float* __restrict__ out) {
    __shared__ __align__(16) float Xs[1024];
    __shared__ __align__(16) float T[1024];
    __shared__ float mu[8], iv[8];
    int tid = threadIdx.x, vb = blockIdx.x;
    const float* X; const float* R; const float* gg; const float* bb;
    float* O; int r0;
    if (vb < 64) { X = attl; R = lige; gg = g_l; bb = be_l; O = out; r0 = vb * 8; }
    else {
        X = attp; R = poce; gg = g_p; bb = be_p;
        O = out + 512 * 128; r0 = (vb - 64) * 8;
    }
    for (int idx = tid; idx < 256; idx += 128)
        ((float4*)Xs)[idx] = ((const float4*)(X + (size_t)r0 * 128))[idx];
    __syncthreads();
    const float4* Xs4 = (const float4*)Xs;
    float acc[8];
    float bv = bias[tid];
    #pragma unroll
    for (int r = 0; r < 8; r++) acc[r] = bv;
    const float4* w4 = (const float4*)(W + (size_t)tid * 128);
    #pragma unroll 4
    for (int kb = 0; kb < 32; kb++) {
        float4 wv = w4[kb];
        #pragma unroll
        for (int r = 0; r < 8; r++) {
            float4 x = Xs4[r * 32 + kb];
            acc[r] = fmaf(x.x, wv.x, acc[r]);
            acc[r] = fmaf(x.y, wv.y, acc[r]);
            acc[r] = fmaf(x.z, wv.z, acc[r]);
            acc[r] = fmaf(x.w, wv.w, acc[r]);
        }
    }
    #pragma unroll
    for (int r = 0; r < 8; r++)
        T[r * 128 + tid] = acc[r] + R[(size_t)(r0 + r) * 128 + tid];
    __syncthreads();

    int wrp = tid >> 5, lane = tid & 31;
    #pragma unroll
    for (int rr = 0; rr < 2; rr++) {
        int r = wrp * 2 + rr;
        float t0 = T[r * 128 + lane], t1 = T[r * 128 + lane + 32];
        float t2 = T[r * 128 + lane + 64], t3 = T[r * 128 + lane + 96];
        float s = (t0 + t1) + (t2 + t3);
        #pragma unroll
        for (int o = 16; o > 0; o >>= 1) s += __shfl_xor_sync(0xffffffffu, s, o);
        float mean = s * (1.f / 128.f);
        float d0 = t0 - mean, d1 = t1 - mean, d2 = t2 - mean, d3 = t3 - mean;
        float v = (d0 * d0 + d1 * d1) + (d2 * d2 + d3 * d3);
        #pragma unroll
        for (int o = 16; o > 0; o >>= 1) v += __shfl_xor_sync(0xffffffffu, v, o);
        if (lane == 0) {
            mu[r] = mean;
            iv[r] = rsqrtf(v * (1.f / 128.f) + 1e-5f);
        }
    }
    __syncthreads();
    float gc = gg[tid], bc = bb[tid];
    #pragma unroll
    for (int r = 0; r < 8; r++) {
        float t = T[r * 128 + tid];
        O[(size_t)(r0 + r) * 128 + tid] = (t - mu[r]) * iv[r] * gc + bc;
    }
}

// ---------------- launch ------------------------------------------------------
extern "C" void kernel_launch(void* const* d_in, const int* in_sizes, int n_in,
                              void* d_out, int out_size) {
    const float* lf   = (const float*)d_in[0];
    const float* pf   = (const float*)d_in[1];
    const float* lc   = (const float*)d_in[2];
    const float* pc   = (const float*)d_in[3];
    const float* Wl   = (const float*)d_in[4];
    const float* bl   = (const float*)d_in[5];
    const float* Wp   = (const float*)d_in[6];
    const float* bp   = (const float*)d_in[7];
    const float* Wd1  = (const float*)d_in[8];
    const float* bd1  = (const float*)d_in[9];
    const float* Wd2  = (const float*)d_in[10];
    const float* bd2  = (const float*)d_in[11];
    const float* Wd3  = (const float*)d_in[12];
    const float* bd3  = (const float*)d_in[13];
    const float* Wgl  = (const float*)d_in[14];
    const float* bgl  = (const float*)d_in[15];
    const float* Wgp  = (const float*)d_in[16];
    const float* bgp  = (const float*)d_in[17];
    const float* Wqkv = (const float*)d_in[18];
    const float* bqkv = (const float*)d_in[19];
    const float* Wo   = (const float*)d_in[20];
    const float* bo   = (const float*)d_in[21];
    const float* g_l  = (const float*)d_in[22];
    const float* be_l = (const float*)d_in[23];
    const float* g_p  = (const float*)d_in[24];
    const float* be_p = (const float*)d_in[25];
    float* out = (float*)d_out;

    float* SB = nullptr;
    cudaGetSymbolAddress((void**)&SB, g_scratch);
    float* s_lig  = SB + OFF_LIG;
    float* s_poc  = SB + OFF_POC;
    float* s_m    = SB + OFF_M;
    float* s_mt   = SB + OFF_MT;
    float* s_aggl = SB + OFF_AGGL;
    float* s_aggp = SB + OFF_AGGP;
    float* s_lige = SB + OFF_LIGE;
    float* s_poce = SB + OFF_POCE;
    float* s_qkvl = SB + OFF_QKVL;
    float* s_qkvp = SB + OFF_QKVP;
    float* s_attl = SB + OFF_ATTL;
    float* s_attp = SB + OFF_ATTP;
    float* s_tab  = SB + OFF_TAB;

    k_pre<<<112, 256>>>(Wd1, bd1, Wd2, bd2, Wd3, bd3, s_tab,
                        lf, pf, Wl, bl, Wp, bp, s_lig, s_poc);
    k_pairm<<<128, 256>>>(lc, pc, s_tab, s_m, s_mt);
    k_aggsoft<<<192, 256>>>(s_m, s_mt, s_poc, s_lig, s_aggl, s_aggp);
    k_gate<<<192, 256>>>(s_lig, s_poc, s_aggl, s_aggp, Wgl, bgl, Wgp, bgp,
                         s_lige, s_poce);
    k_qkv<<<288, 256>>>(s_lige, s_poce, Wqkv, bqkv, s_qkvl, s_qkvp);
    k_flash2<<<dim3(96, 8), 512>>>(s_qkvl, s_qkvp, s_attl, s_attp);
    k_outln<<<192, 128>>>(s_attl, s_attp, Wo, bo, s_lige, s_poce,
                          g_l, be_l, g_p, be_p, out);
}

// round 12
// speedup vs baseline: 1.6256x; 1.0251x over previous
#include <cuda_runtime.h>
#include <math.h>

// ---------------- scratch (device globals; no allocation allowed) ----------
#define OFF_LIG     0           // 512*128
#define OFF_POC     65536       // 1024*128
#define OFF_M       196608      // 512*1024
#define OFF_MT      720896      // 1024*512
#define OFF_AGGL    1245184     // 512*128
#define OFF_AGGP    1310720     // 1024*128
#define OFF_LIGE    1441792     // 512*128
#define OFF_POCE    1507328     // 1024*128
#define OFF_QKVL    1638400     // 512*384
#define OFF_QKVP    1835008     // 1024*384
#define OFF_ATTL    2228224     // 512*128
#define OFF_ATTP    2293760     // 1024*128
#define OFF_TAB     2424832     // 4096
#define SCRATCH_FLOATS 2428928

__device__ float g_scratch[SCRATCH_FLOATS];

#define TAB_N 4096
#define D_MAX 35.0f

// ---------------- f32x2 helpers ----------------------------------------------
__device__ __forceinline__ unsigned long long fma2(unsigned long long a,
                                                   unsigned long long b,
                                                   unsigned long long c) {
    unsigned long long d;
    asm("fma.rn.f32x2 %0, %1, %2, %3;" : "=l"(d) : "l"(a), "l"(b), "l"(c));
    return d;
}
__device__ __forceinline__ unsigned long long mul2(unsigned long long a,
                                                   unsigned long long b) {
    unsigned long long d;
    asm("mul.rn.f32x2 %0, %1, %2;" : "=l"(d) : "l"(a), "l"(b));
    return d;
}
__device__ __forceinline__ unsigned long long add2(unsigned long long a,
                                                   unsigned long long b) {
    unsigned long long d;
    asm("add.rn.f32x2 %0, %1, %2;" : "=l"(d) : "l"(a), "l"(b));
    return d;
}
__device__ __forceinline__ unsigned long long pack2(float x, float y) {
    unsigned long long r;
    asm("mov.b64 %0, {%1, %2};" : "=l"(r) : "f"(x), "f"(y));
    return r;
}
__device__ __forceinline__ void unpack2(unsigned long long v, float& x, float& y) {
    asm("mov.b64 {%0, %1}, %2;" : "=f"(x), "=f"(y) : "l"(v));
}
__device__ __forceinline__ float hsum2(unsigned long long v) {
    float x, y;
    unpack2(v, x, y);
    return x + y;
}

// ---------------- k_pre: 208 blocks x 256 (2 subtiles).
// subs 0..31: distance table slices. subs 32..415: 4-row input-proj tiles. ----
__global__ void __launch_bounds__(256) k_pre(const float* __restrict__ Wd1,
                                             const float* __restrict__ bd1,
                                             const float* __restrict__ Wd2,
                                             const float* __restrict__ bd2,
                                             const float* __restrict__ Wd3,
                                             const float* __restrict__ bd3,
                                             float* __restrict__ tab,
                                             const float* __restrict__ lf,
                                             const float* __restrict__ pf,
                                             const float* __restrict__ Wl,
                                             const float* __restrict__ bl,
                                             const float* __restrict__ Wp,
                                             const float* __restrict__ bp,
                                             float* __restrict__ lig,
                                             float* __restrict__ poc) {
    __shared__ __align__(16) float smem[2 * 2304];
    int tid = threadIdx.x;
    int sub = tid >> 7, st = tid & 127;
    int vb = blockIdx.x * 2 + sub;
    float* sbuf = smem + sub * 2304;          // 2048 data
    float* w1s = sbuf + 2048;                 // 32
    float* b1s = w1s + 32;                    // 32
    float* b2s = b1s + 32;                    // 64
    float* wms = b2s + 64;                    // 64
    float* mcs = wms + 64;                    // 1

    if (vb < 32) {
        // ---- table slice ----
        for (int idx = st; idx < 2048; idx += 128) sbuf[idx] = Wd2[idx];
        if (st < 32) { w1s[st] = Wd1[st]; b1s[st] = bd1[st]; }
        if (st >= 32 && st < 96) b2s[st - 32] = bd2[st - 32];
        if (st < 64) {
            float s = 0.f;
            for (int i = 0; i < 128; i++) s += Wd3[i * 64 + st];
            wms[st] = s * (1.f / 128.f);
        }
        if (st == 127) {
            float s = 0.f;
            for (int i = 0; i < 128; i++) s += bd3[i];
            *mcs = s * (1.f / 128.f);
        }
        __syncthreads();
        int idx = vb * 128 + st;
        float d = (float)idx * (D_MAX / (float)(TAB_N - 1));
        float h1[32];
        #pragma unroll
        for (int k = 0; k < 32; k++) h1[k] = fmaxf(fmaf(d, w1s[k], b1s[k]), 0.f);
        float mval = *mcs;
        #pragma unroll 1
        for (int j = 0; j < 64; j++) {
            const float4* wr = (const float4*)(sbuf + j * 32);
            float a0 = 0.f, a1 = 0.f, a2 = 0.f, a3 = 0.f;
            #pragma unroll
            for (int q = 0; q < 8; q++) {
                float4 w = wr[q];
                a0 = fmaf(w.x, h1[4 * q + 0], a0);
                a1 = fmaf(w.y, h1[4 * q + 1], a1);
                a2 = fmaf(w.z, h1[4 * q + 2], a2);
                a3 = fmaf(w.w, h1[4 * q + 3], a3);
            }
            float pre = b2s[j] + ((a0 + a1) + (a2 + a3));
            mval = fmaf(fmaxf(pre, 0.f), wms[j], mval);
        }
        tab[idx] = mval;
    } else {
        // ---- input projection: 4 rows, f32x2 k-blocked ----
        int pb = vb - 32;                     // 0..383
        const float* X; const float* W; const float* B; float* Y; int r0;
        if (pb < 128) { X = lf; W = Wl; B = bl; Y = lig; r0 = pb * 4; }
        else          { X = pf; W = Wp; B = bp; Y = poc; r0 = (pb - 128) * 4; }
        ((float4*)sbuf)[st] = ((const float4*)(X + (size_t)r0 * 128))[st];
        __syncthreads();
        const ulonglong2* X2 = (const ulonglong2*)sbuf;
        const ulonglong2* w2 = (const ulonglong2*)(W + (size_t)st * 128);
        unsigned long long acc2[4] = {0ull, 0ull, 0ull, 0ull};
        #pragma unroll 8
        for (int kb = 0; kb < 32; kb++) {
            ulonglong2 w = w2[kb];
            #pragma unroll
            for (int r = 0; r < 4; r++) {
                ulonglong2 x = X2[r * 32 + kb];
                acc2[r] = fma2(x.x, w.x, acc2[r]);
                acc2[r] = fma2(x.y, w.y, acc2[r]);
            }
        }
        float bv = B[st];
        #pragma unroll
        for (int r = 0; r < 4; r++)
            Y[(size_t)(r0 + r) * 128 + st] = hsum2(acc2[r]) + bv;
    }
}

// ---------------- pair: m via table lerp, write M and MT ----------------------
__global__ void __launch_bounds__(256) k_pairm(const float* __restrict__ lc,
                                               const float* __restrict__ pc,
                                               const float* __restrict__ tab,
                                               float* __restrict__ M,
                                               float* __restrict__ MT) {
    __shared__ float tabs[TAB_N];
    __shared__ float pcs[3072];
    int tid = threadIdx.x;
    for (int idx = tid; idx < TAB_N; idx += 256) tabs[idx] = tab[idx];
    for (int idx = tid; idx < 3072; idx += 256) pcs[idx] = pc[idx];
    __syncthreads();

    int i0 = blockIdx.x * 4;
    float lx[4], ly[4], lz[4];
    #pragma unroll
    for (int r = 0; r < 4; r++) {
        lx[r] = lc[(i0 + r) * 3 + 0];
        ly[r] = lc[(i0 + r) * 3 + 1];
        lz[r] = lc[(i0 + r) * 3 + 2];
    }
    const float invh = (float)(TAB_N - 1) / D_MAX;
    #pragma unroll
    for (int jj = 0; jj < 4; jj++) {
        int j = jj * 256 + tid;
        float px = pcs[j * 3 + 0], py = pcs[j * 3 + 1], pz = pcs[j * 3 + 2];
        float4 v;
        float* vp = (float*)&v;
        #pragma unroll
        for (int r = 0; r < 4; r++) {
            float dx = lx[r] - px, dy = ly[r] - py, dz = lz[r] - pz;
            float d = sqrtf(fmaf(dx, dx, fmaf(dy, dy, dz * dz)));
            float t = d * invh;
            int t0 = min((int)t, TAB_N - 2);
            float f = t - (float)t0;
            float v0 = tabs[t0], v1 = tabs[t0 + 1];
            vp[r] = fmaf(f, v1 - v0, v0);
            M[(size_t)(i0 + r) * 1024 + j] = vp[r];
        }
        *(float4*)(MT + (size_t)j * 512 + i0) = v;
    }
}

// ---------------- agg with fused softmax, register-blocked GEMM ---------------
__global__ void __launch_bounds__(256) k_aggsoft(const float* __restrict__ M,
                                                 const float* __restrict__ MT,
                                                 const float* __restrict__ poc,
                                                 const float* __restrict__ lig,
                                                 float* __restrict__ aggl,
                                                 float* __restrict__ aggp) {
    __shared__ __align__(16) float As[8192];
    int tid = threadIdx.x, bx = blockIdx.x;
    const float* S; const float* B; float* Y; int r0, K;
    if (bx < 64) { S = M;  B = poc; Y = aggl; r0 = bx * 8;        K = 1024; }
    else         { S = MT; B = lig; Y = aggp; r0 = (bx - 64) * 8; K = 512;  }

    int w = tid >> 5, lane = tid & 31;
    const float* srow = S + (size_t)(r0 + w) * K;
    if (K == 1024) {
        float mv[32];
        float mx = -3.4e38f;
        #pragma unroll
        for (int t = 0; t < 32; t++) {
            float v = -srow[t * 32 + lane];
            mv[t] = v;
            mx = fmaxf(mx, v);
        }
        #pragma unroll
        for (int o = 16; o > 0; o >>= 1)
            mx = fmaxf(mx, __shfl_xor_sync(0xffffffffu, mx, o));
        float sum = 0.f;
        #pragma unroll
        for (int t = 0; t < 32; t++) {
            float e = __expf(mv[t] - mx);
            mv[t] = e;
            sum += e;
        }
        #pragma unroll
        for (int o = 16; o > 0; o >>= 1)
            sum += __shfl_xor_sync(0xffffffffu, sum, o);
        float inv = 1.f / sum;
        #pragma unroll
        for (int t = 0; t < 32; t++) As[(t * 32 + lane) * 8 + w] = mv[t] * inv;
    } else {
        float mv[16];
        float mx = -3.4e38f;
        #pragma unroll
        for (int t = 0; t < 16; t++) {
            float v = -srow[t * 32 + lane];
            mv[t] = v;
            mx = fmaxf(mx, v);
        }
        #pragma unroll
        for (int o = 16; o > 0; o >>= 1)
            mx = fmaxf(mx, __shfl_xor_sync(0xffffffffu, mx, o));
        float sum = 0.f;
        #pragma unroll
        for (int t = 0; t < 16; t++) {
            float e = __expf(mv[t] - mx);
            mv[t] = e;
            sum += e;
        }
        #pragma unroll
        for (int o = 16; o > 0; o >>= 1)
            sum += __shfl_xor_sync(0xffffffffu, sum, o);
        float inv = 1.f / sum;
        #pragma unroll
        for (int t = 0; t < 16; t++) As[(t * 32 + lane) * 8 + w] = mv[t] * inv;
    }
    __syncthreads();

    int cg = tid & 31, ks = tid >> 5;
    int steps = K >> 3;
    int kstart = ks * steps;
    float4 acc4[8];
    #pragma unroll
    for (int r = 0; r < 8; r++) acc4[r] = make_float4(0.f, 0.f, 0.f, 0.f);
    const float4* As4 = (const float4*)As;
    const float4* B4 = (const float4*)B;
    #pragma unroll 2
    for (int kk = 0; kk < steps; kk++) {
        int k = kstart + kk;
        float4 a0 = As4[k * 2 + 0];
        float4 a1 = As4[k * 2 + 1];
        float4 b = B4[(size_t)k * 32 + cg];
        acc4[0].x = fmaf(a0.x, b.x, acc4[0].x); acc4[0].y = fmaf(a0.x, b.y, acc4[0].y);
        acc4[0].z = fmaf(a0.x, b.z, acc4[0].z); acc4[0].w = fmaf(a0.x, b.w, acc4[0].w);
        acc4[1].x = fmaf(a0.y, b.x, acc4[1].x); acc4[1].y = fmaf(a0.y, b.y, acc4[1].y);
        acc4[1].z = fmaf(a0.y, b.z, acc4[1].z); acc4[1].w = fmaf(a0.y, b.w, acc4[1].w);
        acc4[2].x = fmaf(a0.z, b.x, acc4[2].x); acc4[2].y = fmaf(a0.z, b.y, acc4[2].y);
        acc4[2].z = fmaf(a0.z, b.z, acc4[2].z); acc4[2].w = fmaf(a0.z, b.w, acc4[2].w);
        acc4[3].x = fmaf(a0.w, b.x, acc4[3].x); acc4[3].y = fmaf(a0.w, b.y, acc4[3].y);
        acc4[3].z = fmaf(a0.w, b.z, acc4[3].z); acc4[3].w = fmaf(a0.w, b.w, acc4[3].w);
        acc4[4].x = fmaf(a1.x, b.x, acc4[4].x); acc4[4].y = fmaf(a1.x, b.y, acc4[4].y);
        acc4[4].z = fmaf(a1.x, b.z, acc4[4].z); acc4[4].w = fmaf(a1.x, b.w, acc4[4].w);
        acc4[5].x = fmaf(a1.y, b.x, acc4[5].x); acc4[5].y = fmaf(a1.y, b.y, acc4[5].y);
        acc4[5].z = fmaf(a1.y, b.z, acc4[5].z); acc4[5].w = fmaf(a1.y, b.w, acc4[5].w);
        acc4[6].x = fmaf(a1.z, b.x, acc4[6].x); acc4[6].y = fmaf(a1.z, b.y, acc4[6].y);
        acc4[6].z = fmaf(a1.z, b.z, acc4[6].z); acc4[6].w = fmaf(a1.z, b.w, acc4[6].w);
        acc4[7].x = fmaf(a1.w, b.x, acc4[7].x); acc4[7].y = fmaf(a1.w, b.y, acc4[7].y);
        acc4[7].z = fmaf(a1.w, b.z, acc4[7].z); acc4[7].w = fmaf(a1.w, b.w, acc4[7].w);
    }
    __syncthreads();
    float4* P4 = (float4*)As;
    #pragma unroll
    for (int r = 0; r < 8; r++) P4[ks * 256 + r * 32 + cg] = acc4[r];
    __syncthreads();
    float4 s = P4[tid];
    #pragma unroll
    for (int sl = 1; sl < 8; sl++) {
        float4 p = P4[sl * 256 + tid];
        s.x += p.x; s.y += p.y; s.z += p.z; s.w += p.w;
    }
    int r = tid >> 5, cc = tid & 31;
    ((float4*)(Y + (size_t)(r0 + r) * 128))[cc] = s;
}

// ---------------- gate: 384 blocks x 256, 4-row tiles, K split in halves ------
__global__ void __launch_bounds__(256) k_gate(const float* __restrict__ lig,
                                              const float* __restrict__ poc,
                                              const float* __restrict__ aggl,
                                              const float* __restrict__ aggp,
                                              const float* __restrict__ Wgl,
                                              const float* __restrict__ bgl,
                                              const float* __restrict__ Wgp,
                                              const float* __restrict__ bgp,
                                              float* __restrict__ lige,
                                              float* __restrict__ poce) {
    __shared__ __align__(16) float xs[512];
    __shared__ __align__(16) float as_[512];
    __shared__ float red[512];
    int tid = threadIdx.x, vb = blockIdx.x;
    const float* X; const float* A; const float* W; const float* B;
    float* Y; int r0;
    if (vb < 128) { X = lig; A = aggl; W = Wgl; B = bgl; Y = lige; r0 = vb * 4; }
    else { X = poc; A = aggp; W = Wgp; B = bgp; Y = poce; r0 = (vb - 128) * 4; }
    if (tid < 128) ((float4*)xs)[tid] = ((const float4*)(X + (size_t)r0 * 128))[tid];
    else ((float4*)as_)[tid - 128] = ((const float4*)(A + (size_t)r0 * 128))[tid - 128];
    __syncthreads();
    int c = tid & 127, part = tid >> 7;
    const ulonglong2* S2 = (const ulonglong2*)(part ? as_ : xs);
    const ulonglong2* w2 = (const ulonglong2*)(W + (size_t)c * 256 + part * 128);
    unsigned long long acc2[4] = {0ull, 0ull, 0ull, 0ull};
    #pragma unroll 8
    for (int kb = 0; kb < 32; kb++) {
        ulonglong2 w = w2[kb];
        #pragma unroll
        for (int r = 0; r < 4; r++) {
            ulonglong2 x = S2[r * 32 + kb];
            acc2[r] = fma2(x.x, w.x, acc2[r]);
            acc2[r] = fma2(x.y, w.y, acc2[r]);
        }
    }
    if (part) {
        #pragma unroll
        for (int r = 0; r < 4; r++) red[c * 4 + r] = hsum2(acc2[r]);
    }
    __syncthreads();
    if (!part) {
        float bv = B[c];
        #pragma unroll
        for (int r = 0; r < 4; r++) {
            float t = hsum2(acc2[r]) + red[c * 4 + r] + bv;
            float g = 1.f / (1.f + __expf(-t));
            float xv = xs[r * 128 + c], av = as_[r * 128 + c];
            Y[(size_t)(r0 + r) * 128 + c] = g * xv + (1.f - g) * av;
        }
    }
}

// ---------------- qkv: 576 blocks x 128, 8-row tiles ---------------------------
__global__ void __launch_bounds__(128) k_qkv(const float* __restrict__ lige,
                                             const float* __restrict__ poce,
                                             const float* __restrict__ W,
                                             const float* __restrict__ B,
                                             float* __restrict__ qkvl,
                                             float* __restrict__ qkvp) {
    __shared__ __align__(16) float Xs[1024];
    int tid = threadIdx.x, vb = blockIdx.x;
    int p = vb / 192, tile = vb % 192;
    const float* X; float* Y; int r0;
    if (tile < 64) { X = lige; Y = qkvl; r0 = tile * 8; }
    else           { X = poce; Y = qkvp; r0 = (tile - 64) * 8; }
    ((float4*)Xs)[tid] = ((const float4*)(X + (size_t)r0 * 128))[tid];
    ((float4*)Xs)[tid + 128] = ((const float4*)(X + (size_t)r0 * 128))[tid + 128];
    __syncthreads();
    const ulonglong2* X2 = (const ulonglong2*)Xs;
    int c = p * 128 + tid;
    const ulonglong2* w2 = (const ulonglong2*)(W + (size_t)c * 128);
    unsigned long long acc2[8] = {0ull, 0ull, 0ull, 0ull, 0ull, 0ull, 0ull, 0ull};
    #pragma unroll 4
    for (int kb = 0; kb < 32; kb++) {
        ulonglong2 w = w2[kb];
        #pragma unroll
        for (int r = 0; r < 8; r++) {
            ulonglong2 x = X2[r * 32 + kb];
            acc2[r] = fma2(x.x, w.x, acc2[r]);
            acc2[r] = fma2(x.y, w.y, acc2[r]);
        }
    }
    float bv = B[c];
    #pragma unroll
    for (int r = 0; r < 8; r++)
        Y[(size_t)(r0 + r) * 384 + c] = hsum2(acc2[r]) + bv;
}

// ---------------- flash attention: 2 queries/warp, f32x2 AV --------------------
// grid(96, 8), block 256 = 8 warps x 2 queries = 16 queries/block.
__global__ void __launch_bounds__(256) k_flash2(const float* __restrict__ qkvl,
                                                const float* __restrict__ qkvp,
                                                float* __restrict__ attl,
                                                float* __restrict__ attp) {
    __shared__ __align__(16) float4 Ks[128 * 5];
    __shared__ __align__(16) float4 Vs[128 * 5];
    int bx = blockIdx.x, h = blockIdx.y;
    int tid = threadIdx.x, w = tid >> 5, lane = tid & 31;
    const float* Qb; const float* KVb; float* outp; int nk, iA;
    if (bx < 32) { Qb = qkvl; KVb = qkvp; outp = attl; nk = 1024; iA = bx * 16 + w * 2; }
    else         { Qb = qkvp; KVb = qkvl; outp = attp; nk = 512; iA = (bx - 32) * 16 + w * 2; }

    const float* qpA = Qb + (size_t)iA * 384 + h * 16;
    float4 qA0 = ((const float4*)qpA)[0], qA1 = ((const float4*)qpA)[1];
    float4 qA2 = ((const float4*)qpA)[2], qA3 = ((const float4*)qpA)[3];
    const float* qpB = qpA + 384;
    float4 qB0 = ((const float4*)qpB)[0], qB1 = ((const float4*)qpB)[1];
    float4 qB2 = ((const float4*)qpB)[2], qB3 = ((const float4*)qpB)[3];

    float mA = -3.4e38f, lA = 0.f, mB = -3.4e38f, lB = 0.f;
    unsigned long long accA[8], accB[8];
    #pragma unroll
    for (int q = 0; q < 8; q++) { accA[q] = 0ull; accB[q] = 0ull; }

    int jload = tid >> 1, cl = (tid & 1) * 2;
    const float* kb0 = KVb + (size_t)jload * 384 + 128 + h * 16 + cl * 4;

    for (int jb = 0; jb < nk; jb += 128) {
        __syncthreads();
        const float* src = kb0 + (size_t)jb * 384;
        Ks[jload * 5 + cl]     = *(const float4*)(src);
        Ks[jload * 5 + cl + 1] = *(const float4*)(src + 4);
        Vs[jload * 5 + cl]     = *(const float4*)(src + 128);
        Vs[jload * 5 + cl + 1] = *(const float4*)(src + 132);
        __syncthreads();

        float sA[4], sB[4];
        #pragma unroll
        for (int jj = 0; jj < 4; jj++) {
            const float4* kr = Ks + (jj * 32 + lane) * 5;
            float4 k0 = kr[0], k1 = kr[1], k2 = kr[2], k3 = kr[3];
            float tA = qA0.x * k0.x;
            tA = fmaf(qA0.y, k0.y, tA); tA = fmaf(qA0.z, k0.z, tA); tA = fmaf(qA0.w, k0.w, tA);
            tA = fmaf(qA1.x, k1.x, tA); tA = fmaf(qA1.y, k1.y, tA);
            tA = fmaf(qA1.z, k1.z, tA); tA = fmaf(qA1.w, k1.w, tA);
            tA = fmaf(qA2.x, k2.x, tA); tA = fmaf(qA2.y, k2.y, tA);
            tA = fmaf(qA2.z, k2.z, tA); tA = fmaf(qA2.w, k2.w, tA);
            tA = fmaf(qA3.x, k3.x, tA); tA = fmaf(qA3.y, k3.y, tA);
            tA = fmaf(qA3.z, k3.z, tA); tA = fmaf(qA3.w, k3.w, tA);
            float tB = qB0.x * k0.x;
            tB = fmaf(qB0.y, k0.y, tB); tB = fmaf(qB0.z, k0.z, tB); tB = fmaf(qB0.w, k0.w, tB);
            tB = fmaf(qB1.x, k1.x, tB); tB = fmaf(qB1.y, k1.y, tB);
            tB = fmaf(qB1.z, k1.z, tB); tB = fmaf(qB1.w, k1.w, tB);
            tB = fmaf(qB2.x, k2.x, tB); tB = fmaf(qB2.y, k2.y, tB);
            tB = fmaf(qB2.z, k2.z, tB); tB = fmaf(qB2.w, k2.w, tB);
            tB = fmaf(qB3.x, k3.x, tB); tB = fmaf(qB3.y, k3.y, tB);
            tB = fmaf(qB3.z, k3.z, tB); tB = fmaf(qB3.w, k3.w, tB);
            sA[jj] = tA * 0.25f;
            sB[jj] = tB * 0.25f;
        }
        float txA = fmaxf(fmaxf(sA[0], sA[1]), fmaxf(sA[2], sA[3]));
        float txB = fmaxf(fmaxf(sB[0], sB[1]), fmaxf(sB[2], sB[3]));
        #pragma unroll
        for (int o = 16; o > 0; o >>= 1) {
            txA = fmaxf(txA, __shfl_xor_sync(0xffffffffu, txA, o));
            txB = fmaxf(txB, __shfl_xor_sync(0xffffffffu, txB, o));
        }
        float mnA = fmaxf(mA, txA), cA = __expf(mA - mnA);
        float mnB = fmaxf(mB, txB), cB = __expf(mB - mnB);
        mA = mnA; mB = mnB; lA *= cA; lB *= cB;
        unsigned long long cA2 = pack2(cA, cA), cB2 = pack2(cB, cB);
        #pragma unroll
        for (int q = 0; q < 8; q++) {
            accA[q] = mul2(accA[q], cA2);
            accB[q] = mul2(accB[q], cB2);
        }
        #pragma unroll
        for (int jj = 0; jj < 4; jj++) {
            float pA = __expf(sA[jj] - mA);
            float pB = __expf(sB[jj] - mB);
            lA += pA; lB += pB;
            unsigned long long pA2 = pack2(pA, pA), pB2 = pack2(pB, pB);
            const ulonglong2* vr = (const ulonglong2*)(Vs + (jj * 32 + lane) * 5);
            #pragma unroll
            for (int q = 0; q < 4; q++) {
                ulonglong2 v = vr[q];
                accA[q * 2]     = fma2(pA2, v.x, accA[q * 2]);
                accA[q * 2 + 1] = fma2(pA2, v.y, accA[q * 2 + 1]);
                accB[q * 2]     = fma2(pB2, v.x, accB[q * 2]);
                accB[q * 2 + 1] = fma2(pB2, v.y, accB[q * 2 + 1]);
            }
        }
    }

    #pragma unroll
    for (int o = 16; o > 0; o >>= 1) {
        lA += __shfl_xor_sync(0xffffffffu, lA, o);
        lB += __shfl_xor_sync(0xffffffffu, lB, o);
    }
    #pragma unroll
    for (int q = 0; q < 8; q++) {
        #pragma unroll
        for (int o = 16; o > 0; o >>= 1) {
            accA[q] = add2(accA[q], __shfl_xor_sync(0xffffffffu, accA[q], o));
            accB[q] = add2(accB[q], __shfl_xor_sync(0xffffffffu, accB[q], o));
        }
    }
    if (lane < 16) {
        float x, y;
        unpack2(accA[lane >> 1], x, y);
        float val = (lane & 1) ? y : x;
        outp[(size_t)iA * 128 + h * 16 + lane] = val * (1.f / lA);
    } else {
        int ll = lane - 16;
        float x, y;
        unpack2(accB[ll >> 1], x, y);
        float val = (ll & 1) ? y : x;
        outp[(size_t)(iA + 1) * 128 + h * 16 + ll] = val * (1.f / lB);
    }
}

// ---------------- out-proj + residual + LN: 384 blocks x 128, 4-row tiles -----
__global__ void __launch_bounds__(128) k_outln(const float* __restrict__ attl,
                                               const float* __restrict__ attp,
                                               const float* __restrict__ W,
                                               const float* __restrict__ bias,
                                               const float* __restrict__ lige,
                                               const float* __restrict__ poce,
                                               const float* __restrict__ g_l,
                                               const float* __restrict__ be_l,
                                               const float* __restrict__ g_p,
                                               const float* __restrict__ be_p,
                                               float* __restrict__ out) {
    __shared__ __align__(16) float Xs[512];
    __shared__ __align__(16) float T[512];
    __shared__ float mu[4], iv[4];
    int tid = threadIdx.x, vb = blockIdx.x;
    const float* X; const float* R; const float* gg; const float* bb;
    float* O; int r0;
    if (vb < 128) { X = attl; R = lige; gg = g_l; bb = be_l; O = out; r0 = vb * 4; }
    else {
        X = attp; R = poce; gg = g_p; bb = be_p;
        O = out + 512 * 128; r0 = (vb - 128) * 4;
    }
    ((float4*)Xs)[tid] = ((const float4*)(X + (size_t)r0 * 128))[tid];
    __syncthreads();
    const ulonglong2* X2 = (const ulonglong2*)Xs;
    const ulonglong2* w2 = (const ulonglong2*)(W + (size_t)tid * 128);
    unsigned long long acc2[4] = {0ull, 0ull, 0ull, 0ull};
    #pragma unroll 8
    for (int kb = 0; kb < 32; kb++) {
        ulonglong2 w = w2[kb];
        #pragma unroll
        for (int r = 0; r < 4; r++) {
            ulonglong2 x = X2[r * 32 + kb];
            acc2[r] = fma2(x.x, w.x, acc2[r]);
            acc2[r] = fma2(x.y, w.y, acc2[r]);
        }
    }
    float bv = bias[tid];
    #pragma unroll
    for (int r = 0; r < 4; r++)
        T[r * 128 + tid] = hsum2(acc2[r]) + bv + R[(size_t)(r0 + r) * 128 + tid];
    __syncthreads();

    int wrp = tid >> 5, lane = tid & 31;
    {
        int r = wrp;
        float t0 = T[r * 128 + lane], t1 = T[r * 128 + lane + 32];
        float t2 = T[r * 128 + lane + 64], t3 = T[r * 128 + lane + 96];
        float s = (t0 + t1) + (t2 + t3);
        #pragma unroll
        for (int o = 16; o > 0; o >>= 1) s += __shfl_xor_sync(0xffffffffu, s, o);
        float mean = s * (1.f / 128.f);
        float d0 = t0 - mean, d1 = t1 - mean, d2 = t2 - mean, d3 = t3 - mean;
        float v = (d0 * d0 + d1 * d1) + (d2 * d2 + d3 * d3);
        #pragma unroll
        for (int o = 16; o > 0; o >>= 1) v += __shfl_xor_sync(0xffffffffu, v, o);
        if (lane == 0) {
            mu[r] = mean;
            iv[r] = rsqrtf(v * (1.f / 128.f) + 1e-5f);
        }
    }
    __syncthreads();
    float gc = gg[tid], bc = bb[tid];
    #pragma unroll
    for (int r = 0; r < 4; r++) {
        float t = T[r * 128 + tid];
        O[(size_t)(r0 + r) * 128 + tid] = (t - mu[r]) * iv[r] * gc + bc;
    }
}

// ---------------- launch ------------------------------------------------------
extern "C" void kernel_launch(void* const* d_in, const int* in_sizes, int n_in,
                              void* d_out, int out_size) {
    const float* lf   = (const float*)d_in[0];
    const float* pf   = (const float*)d_in[1];
    const float* lc   = (const float*)d_in[2];
    const float* pc   = (const float*)d_in[3];
    const float* Wl   = (const float*)d_in[4];
    const float* bl   = (const float*)d_in[5];
    const float* Wp   = (const float*)d_in[6];
    const float* bp   = (const float*)d_in[7];
    const float* Wd1  = (const float*)d_in[8];
    const float* bd1  = (const float*)d_in[9];
    const float* Wd2  = (const float*)d_in[10];
    const float* bd2  = (const float*)d_in[11];
    const float* Wd3  = (const float*)d_in[12];
    const float* bd3  = (const float*)d_in[13];
    const float* Wgl  = (const float*)d_in[14];
    const float* bgl  = (const float*)d_in[15];
    const float* Wgp  = (const float*)d_in[16];
    const float* bgp  = (const float*)d_in[17];
    const float* Wqkv = (const float*)d_in[18];
    const float* bqkv = (const float*)d_in[19];
    const float* Wo   = (const float*)d_in[20];
    const float* bo   = (const float*)d_in[21];
    const float* g_l  = (const float*)d_in[22];
    const float* be_l = (const float*)d_in[23];
    const float* g_p  = (const float*)d_in[24];
    const float* be_p = (const float*)d_in[25];
    float* out = (float*)d_out;

    float* SB = nullptr;
    cudaGetSymbolAddress((void**)&SB, g_scratch);
    float* s_lig  = SB + OFF_LIG;
    float* s_poc  = SB + OFF_POC;
    float* s_m    = SB + OFF_M;
    float* s_mt   = SB + OFF_MT;
    float* s_aggl = SB + OFF_AGGL;
    float* s_aggp = SB + OFF_AGGP;
    float* s_lige = SB + OFF_LIGE;
    float* s_poce = SB + OFF_POCE;
    float* s_qkvl = SB + OFF_QKVL;
    float* s_qkvp = SB + OFF_QKVP;
    float* s_attl = SB + OFF_ATTL;
    float* s_attp = SB + OFF_ATTP;
    float* s_tab  = SB + OFF_TAB;

    k_pre<<<208, 256>>>(Wd1, bd1, Wd2, bd2, Wd3, bd3, s_tab,
                        lf, pf, Wl, bl, Wp, bp, s_lig, s_poc);
    k_pairm<<<128, 256>>>(lc, pc, s_tab, s_m, s_mt);
    k_aggsoft<<<192, 256>>>(s_m, s_mt, s_poc, s_lig, s_aggl, s_aggp);
    k_gate<<<384, 256>>>(s_lig, s_poc, s_aggl, s_aggp, Wgl, bgl, Wgp, bgp,
                         s_lige, s_poce);
    k_qkv<<<576, 128>>>(s_lige, s_poce, Wqkv, bqkv, s_qkvl, s_qkvp);
    k_flash2<<<dim3(96, 8), 256>>>(s_qkvl, s_qkvp, s_attl, s_attp);
    k_outln<<<384, 128>>>(s_attl, s_attp, Wo, bo, s_lige, s_poce,
                          g_l, be_l, g_p, be_p, out);
}